// round 3
// baseline (speedup 1.0000x reference)
#include <cuda_runtime.h>
#include <math.h>

#define LSEQ 200
#define LPAD 208
#define CHUNK 104
#define HSTR 208    // histT row stride (floats)
#define H0STR 108   // h0T row stride (floats)
#define B_MAX 4096

__device__ float g_xbuf[B_MAX * 244];

typedef unsigned long long u64t;

__device__ __forceinline__ u64t dup2(float x) {
    u64t r; asm("mov.b64 %0, {%1, %1};" : "=l"(r) : "f"(x)); return r;
}
__device__ __forceinline__ void fma2(u64t& d, u64t a, u64t b) {
    asm("fma.rn.f32x2 %0, %1, %2, %0;" : "+l"(d) : "l"(a), "l"(b));
}
__device__ __forceinline__ void unpack2(u64t v, float& a, float& b) {
    asm("mov.b64 {%0, %1}, %2;" : "=f"(a), "=f"(b) : "l"(v));
}

struct __align__(16) SmemA {
    float histT[64 * HSTR];   // [k][l], cols 200..207 zero
    float h0T[64 * H0STR];    // [j][l_local] for current chunk
    float M[64 * 64];         // [k][j]
    float aW1s[64 * 32];      // [k][j2]
    float t[64];
    float c[64];
    float aW2s[32];
    float ab1s[32];
    float scores[LPAD];
    float red[32];
    float pool4[256];
    float spart[4 * CHUNK];   // [jg2][l_local]
};

__global__ __launch_bounds__(256, 2) void attn_kernel(
    const int* __restrict__ user_id, const int* __restrict__ item_id,
    const int* __restrict__ item_category, const int* __restrict__ item_dur_bkt,
    const float* __restrict__ user_dense, const float* __restrict__ item_dense,
    const int* __restrict__ history_seq,
    const float* __restrict__ user_W, const float* __restrict__ item_W,
    const float* __restrict__ cat_W, const float* __restrict__ dur_W,
    const float* __restrict__ hist_W,
    const float* __restrict__ aW0, const float* __restrict__ ab0,
    const float* __restrict__ aW1, const float* __restrict__ ab1,
    const float* __restrict__ aW2, const float* __restrict__ ab2)
{
    extern __shared__ char smem_raw[];
    SmemA& S = *reinterpret_cast<SmemA*>(smem_raw);
    const int b = blockIdx.x;
    const int tid = threadIdx.x;

    // ---- load t, weights, init scores ----
    if (tid < 64) S.t[tid] = item_W[item_id[b] * 64 + tid];
    for (int p = tid; p < 2048; p += 256) S.aW1s[p] = aW1[p];
    if (tid < 32) { S.aW2s[tid] = aW2[tid]; S.ab1s[tid] = ab1[tid]; }
    {
        float ab2v = ab2[0];
        for (int p = tid; p < LPAD; p += 256) S.scores[p] = ab2v;
    }
    __syncthreads();

    // ---- M[k][j] = aW0[k][j] + aW0[192+k][j] + t[k]*aW0[128+k][j] ----
    for (int idx = tid; idx < 4096; idx += 256) {
        int k = idx >> 6, j = idx & 63;
        S.M[idx] = aW0[idx] + aW0[(192 + k) * 64 + j] + S.t[k] * aW0[(128 + k) * 64 + j];
    }
    // ---- c[j] = ab0[j] + sum_k t[k]*(aW0[64+k][j] - aW0[192+k][j]) ----
    if (tid < 64) {
        float s = ab0[tid];
        #pragma unroll 8
        for (int k = 0; k < 64; k++)
            s += S.t[k] * (aW0[(64 + k) * 64 + tid] - aW0[(192 + k) * 64 + tid]);
        S.c[tid] = s;
    }
    // ---- gather history rows transposed into histT ----
    {
        int wid = tid >> 5, lane = tid & 31;
        for (int l = wid; l < LSEQ; l += 8) {
            int row = history_seq[b * LSEQ + l];
            float2 v = *(const float2*)&hist_W[row * 64 + lane * 2];
            S.histT[(lane * 2) * HSTR + l]     = v.x;
            S.histT[(lane * 2 + 1) * HSTR + l] = v.y;
        }
    }
    for (int p = tid; p < 64 * 8; p += 256)
        S.histT[(p >> 3) * HSTR + 200 + (p & 7)] = 0.f;
    __syncthreads();

    // ---- two l-chunks of 104 ----
    for (int c0 = 0; c0 < LPAD; c0 += CHUNK) {
        // GEMM1: h0[l][j] = relu(sum_k histT[k][l]*M[k][j] + c[j]); 8l x 8j tiles
        if (tid < 104) {
            int lg = tid % 13, jg = tid / 13;
            const float* hrow = &S.histT[c0 + lg * 8];
            const float* mrow = &S.M[jg * 8];
            u64t acc[4][8];
            #pragma unroll
            for (int jj = 0; jj < 8; jj++) {
                u64t cv = dup2(S.c[jg * 8 + jj]);
                acc[0][jj] = cv; acc[1][jj] = cv; acc[2][jj] = cv; acc[3][jj] = cv;
            }
            #pragma unroll 4
            for (int k = 0; k < 64; k++) {
                ulonglong2 a01 = *(const ulonglong2*)(hrow + k * HSTR);
                ulonglong2 a23 = *(const ulonglong2*)(hrow + k * HSTR + 4);
                float4 bv0 = *(const float4*)(mrow + (k << 6));
                float4 bv1 = *(const float4*)(mrow + (k << 6) + 4);
                u64t bd[8];
                bd[0] = dup2(bv0.x); bd[1] = dup2(bv0.y); bd[2] = dup2(bv0.z); bd[3] = dup2(bv0.w);
                bd[4] = dup2(bv1.x); bd[5] = dup2(bv1.y); bd[6] = dup2(bv1.z); bd[7] = dup2(bv1.w);
                #pragma unroll
                for (int jj = 0; jj < 8; jj++) {
                    fma2(acc[0][jj], a01.x, bd[jj]);
                    fma2(acc[1][jj], a01.y, bd[jj]);
                    fma2(acc[2][jj], a23.x, bd[jj]);
                    fma2(acc[3][jj], a23.y, bd[jj]);
                }
            }
            #pragma unroll
            for (int jj = 0; jj < 8; jj++) {
                float v0, v1, v2, v3, v4, v5, v6, v7;
                unpack2(acc[0][jj], v0, v1);
                unpack2(acc[1][jj], v2, v3);
                unpack2(acc[2][jj], v4, v5);
                unpack2(acc[3][jj], v6, v7);
                int j = jg * 8 + jj;
                float* dst = &S.h0T[j * H0STR + lg * 8];
                *(float4*)dst = make_float4(fmaxf(v0, 0.f), fmaxf(v1, 0.f), fmaxf(v2, 0.f), fmaxf(v3, 0.f));
                *(float4*)(dst + 4) = make_float4(fmaxf(v4, 0.f), fmaxf(v5, 0.f), fmaxf(v6, 0.f), fmaxf(v7, 0.f));
            }
        }
        __syncthreads();

        // GEMM2: h1[l][j2] = relu(sum_k h0[l][k]*aW1[k][j2]+ab1); 8l x 8j tiles (j2=32)
        if (tid < 52) {
            int lg = tid % 13, jg2 = tid / 13;
            const float* arow = &S.h0T[lg * 8];
            const float* wrow = &S.aW1s[jg2 * 8];
            u64t acc[4][8];
            #pragma unroll
            for (int jj = 0; jj < 8; jj++) {
                u64t bv = dup2(S.ab1s[jg2 * 8 + jj]);
                acc[0][jj] = bv; acc[1][jj] = bv; acc[2][jj] = bv; acc[3][jj] = bv;
            }
            #pragma unroll 4
            for (int k = 0; k < 64; k++) {
                ulonglong2 a01 = *(const ulonglong2*)(arow + k * H0STR);
                ulonglong2 a23 = *(const ulonglong2*)(arow + k * H0STR + 4);
                float4 wv0 = *(const float4*)(wrow + (k << 5));
                float4 wv1 = *(const float4*)(wrow + (k << 5) + 4);
                u64t bd[8];
                bd[0] = dup2(wv0.x); bd[1] = dup2(wv0.y); bd[2] = dup2(wv0.z); bd[3] = dup2(wv0.w);
                bd[4] = dup2(wv1.x); bd[5] = dup2(wv1.y); bd[6] = dup2(wv1.z); bd[7] = dup2(wv1.w);
                #pragma unroll
                for (int jj = 0; jj < 8; jj++) {
                    fma2(acc[0][jj], a01.x, bd[jj]);
                    fma2(acc[1][jj], a01.y, bd[jj]);
                    fma2(acc[2][jj], a23.x, bd[jj]);
                    fma2(acc[3][jj], a23.y, bd[jj]);
                }
            }
            // epilogue: scores partial = sum_j relu(h1)*aW2[j]
            float sl[8];
            #pragma unroll
            for (int li = 0; li < 8; li++) sl[li] = 0.f;
            #pragma unroll
            for (int jj = 0; jj < 8; jj++) {
                float w2 = S.aW2s[jg2 * 8 + jj];
                #pragma unroll
                for (int p = 0; p < 4; p++) {
                    float x0, x1;
                    unpack2(acc[p][jj], x0, x1);
                    sl[2 * p]     += fmaxf(x0, 0.f) * w2;
                    sl[2 * p + 1] += fmaxf(x1, 0.f) * w2;
                }
            }
            #pragma unroll
            for (int li = 0; li < 8; li++)
                S.spart[jg2 * CHUNK + lg * 8 + li] = sl[li];
        }
        __syncthreads();
        // reduce 4 jg2-partials into scores
        if (tid < CHUNK) {
            int l = c0 + tid;
            if (l < LSEQ)
                S.scores[l] += S.spart[tid] + S.spart[CHUNK + tid]
                             + S.spart[2 * CHUNK + tid] + S.spart[3 * CHUNK + tid];
        }
        // next G1 writes h0T (disjoint from spart/scores); next G2 separated by sync
    }
    __syncthreads();

    // ---- mask + softmax over L ----
    {
        float s = -3.402823466e38f;
        if (tid < LSEQ) {
            s = S.scores[tid];
            if (history_seq[b * LSEQ + tid] == 0) s = -1.0e9f;
        }
        float v = s;
        #pragma unroll
        for (int o = 16; o; o >>= 1) v = fmaxf(v, __shfl_xor_sync(0xffffffffu, v, o));
        if ((tid & 31) == 0) S.red[tid >> 5] = v;
        __syncthreads();
        if (tid < 32) {
            float r = (tid < 8) ? S.red[tid] : -3.402823466e38f;
            #pragma unroll
            for (int o = 4; o; o >>= 1) r = fmaxf(r, __shfl_xor_sync(0xffffffffu, r, o));
            if (tid == 0) S.red[8] = r;
        }
        __syncthreads();
        float mx = S.red[8];
        float e = (tid < LSEQ) ? expf(s - mx) : 0.f;
        float v2 = e;
        #pragma unroll
        for (int o = 16; o; o >>= 1) v2 += __shfl_xor_sync(0xffffffffu, v2, o);
        if ((tid & 31) == 0) S.red[tid >> 5] = v2;
        __syncthreads();
        if (tid < 32) {
            float r = (tid < 8) ? S.red[tid] : 0.f;
            #pragma unroll
            for (int o = 4; o; o >>= 1) r += __shfl_xor_sync(0xffffffffu, r, o);
            if (tid == 0) S.red[8] = r;
        }
        __syncthreads();
        float inv = 1.f / S.red[8];
        if (tid < LSEQ) S.scores[tid] = e * inv;
    }
    __syncthreads();

    // ---- pooled[k] = sum_l w[l]*histT[k][l] ----
    {
        int k = tid & 63, g = tid >> 6;
        float p = 0.f;
        for (int l = g; l < LSEQ; l += 4) p += S.histT[k * HSTR + l] * S.scores[l];
        S.pool4[(g << 6) + k] = p;
    }
    __syncthreads();
    if (tid < 64) {
        float pooled = S.pool4[tid] + S.pool4[64 + tid] + S.pool4[128 + tid] + S.pool4[192 + tid];
        g_xbuf[b * 244 + 180 + tid] = pooled;
    }
    // ---- assemble x ----
    if (tid < 64) {
        g_xbuf[b * 244 + tid] = user_W[user_id[b] * 64 + tid];
    } else if (tid < 128) {
        g_xbuf[b * 244 + tid] = S.t[tid - 64];
    } else if (tid < 144) {
        g_xbuf[b * 244 + tid] = cat_W[item_category[b] * 16 + (tid - 128)];
    } else if (tid < 152) {
        g_xbuf[b * 244 + tid] = dur_W[item_dur_bkt[b] * 8 + (tid - 144)];
    } else if (tid < 177) {
        g_xbuf[b * 244 + tid] = user_dense[b * 25 + (tid - 152)];
    } else if (tid < 180) {
        g_xbuf[b * 244 + tid] = item_dense[b * 3 + (tid - 177)];
    }
}

// ---- MLP: 8 samples per block, samples packed along f32x2 ----
__global__ __launch_bounds__(256) void mlp_kernel(
    const float* __restrict__ mW0, const float* __restrict__ mb0,
    const float* __restrict__ mW1, const float* __restrict__ mb1,
    const float* __restrict__ mW2, const float* __restrict__ mb2,
    float* __restrict__ out, int B)
{
    __shared__ __align__(16) float xsT[244 * 8];
    __shared__ __align__(16) float h0T[256 * 8];
    __shared__ __align__(16) float h1s[8 * 128];
    const int b0 = blockIdx.x * 8;
    const int tid = threadIdx.x;

    #pragma unroll
    for (int q = 0; q < 8; q++) {
        if (tid < 244 && (b0 + q) < B)
            xsT[tid * 8 + q] = g_xbuf[(b0 + q) * 244 + tid];
    }
    __syncthreads();

    {
        u64t acc[4];
        u64t bias = dup2(mb0[tid]);
        #pragma unroll
        for (int p = 0; p < 4; p++) acc[p] = bias;
        #pragma unroll 4
        for (int i = 0; i < 244; i++) {
            u64t wd = dup2(mW0[i * 256 + tid]);
            ulonglong2 x01 = *(const ulonglong2*)&xsT[i * 8];
            ulonglong2 x23 = *(const ulonglong2*)&xsT[i * 8 + 4];
            fma2(acc[0], x01.x, wd); fma2(acc[1], x01.y, wd);
            fma2(acc[2], x23.x, wd); fma2(acc[3], x23.y, wd);
        }
        #pragma unroll
        for (int p = 0; p < 4; p++) {
            float a, c;
            unpack2(acc[p], a, c);
            h0T[tid * 8 + 2 * p]     = fmaxf(a, 0.f);
            h0T[tid * 8 + 2 * p + 1] = fmaxf(c, 0.f);
        }
    }
    __syncthreads();

    {
        int j = tid & 127, h = tid >> 7;
        u64t bias = dup2(mb1[j]);
        u64t acc[2] = {bias, bias};
        #pragma unroll 4
        for (int i = 0; i < 256; i++) {
            u64t wd = dup2(mW1[i * 128 + j]);
            ulonglong2 a = *(const ulonglong2*)&h0T[i * 8 + h * 4];
            fma2(acc[0], a.x, wd); fma2(acc[1], a.y, wd);
        }
        #pragma unroll
        for (int p = 0; p < 2; p++) {
            float a, c;
            unpack2(acc[p], a, c);
            h1s[(h * 4 + 2 * p) * 128 + j]     = fmaxf(a, 0.f);
            h1s[(h * 4 + 2 * p + 1) * 128 + j] = fmaxf(c, 0.f);
        }
    }
    __syncthreads();

    {
        int w = tid >> 5, lane = tid & 31;
        float m0 = mW2[lane], m1 = mW2[lane + 32], m2 = mW2[lane + 64], m3 = mW2[lane + 96];
        const float* hp = &h1s[w * 128];
        float v = hp[lane] * m0 + hp[lane + 32] * m1 + hp[lane + 64] * m2 + hp[lane + 96] * m3;
        #pragma unroll
        for (int o = 16; o; o >>= 1) v += __shfl_xor_sync(0xffffffffu, v, o);
        if (lane == 0 && (b0 + w) < B) {
            float logit = v + mb2[0];
            out[b0 + w] = 1.f / (1.f + expf(-logit));
        }
    }
}

extern "C" void kernel_launch(void* const* d_in, const int* in_sizes, int n_in,
                              void* d_out, int out_size)
{
    const int*   user_id       = (const int*)d_in[0];
    const int*   item_id       = (const int*)d_in[1];
    const int*   item_category = (const int*)d_in[2];
    const int*   item_dur_bkt  = (const int*)d_in[3];
    const float* user_dense    = (const float*)d_in[4];
    const float* item_dense    = (const float*)d_in[5];
    const int*   history_seq   = (const int*)d_in[6];
    const float* user_W        = (const float*)d_in[7];
    const float* item_W        = (const float*)d_in[8];
    const float* cat_W         = (const float*)d_in[9];
    const float* dur_W         = (const float*)d_in[10];
    const float* hist_W        = (const float*)d_in[11];
    const float* aW0 = (const float*)d_in[12];
    const float* ab0 = (const float*)d_in[13];
    const float* aW1 = (const float*)d_in[14];
    const float* ab1 = (const float*)d_in[15];
    const float* aW2 = (const float*)d_in[16];
    const float* ab2 = (const float*)d_in[17];
    const float* mW0 = (const float*)d_in[18];
    const float* mb0 = (const float*)d_in[19];
    const float* mW1 = (const float*)d_in[20];
    const float* mb1 = (const float*)d_in[21];
    const float* mW2 = (const float*)d_in[22];
    const float* mb2 = (const float*)d_in[23];

    const int B = in_sizes[0];
    float* out = (float*)d_out;

    cudaFuncSetAttribute(attn_kernel, cudaFuncAttributeMaxDynamicSharedMemorySize,
                         (int)sizeof(SmemA));

    attn_kernel<<<B, 256, sizeof(SmemA)>>>(
        user_id, item_id, item_category, item_dur_bkt,
        user_dense, item_dense, history_seq,
        user_W, item_W, cat_W, dur_W, hist_W,
        aW0, ab0, aW1, ab1, aW2, ab2);

    mlp_kernel<<<(B + 7) / 8, 256>>>(mW0, mb0, mW1, mb1, mW2, mb2, out, B);
}

// round 5
// speedup vs baseline: 1.3634x; 1.3634x over previous
#include <cuda_runtime.h>
#include <math.h>

#define LSEQ 200
#define LPAD 208
#define CHUNK 52
#define NLG 13
#define HSTR 212
#define B_MAX 4096

__device__ float g_xbuf[B_MAX * 244];

typedef unsigned long long u64t;

__device__ __forceinline__ u64t dup2(float x) {
    u64t r; asm("mov.b64 %0, {%1, %1};" : "=l"(r) : "f"(x)); return r;
}
__device__ __forceinline__ void fma2(u64t& d, u64t a, u64t b) {
    asm("fma.rn.f32x2 %0, %1, %2, %0;" : "+l"(d) : "l"(a), "l"(b));
}
__device__ __forceinline__ void unpack2(u64t v, float& a, float& b) {
    asm("mov.b64 {%0, %1}, %2;" : "=f"(a), "=f"(b) : "l"(v));
}

struct __align__(16) SmemA {
    float histT[64 * HSTR];  // [k][l], cols 200..207 zero
    float h0T[64 * 64];      // [j][cg*4+li], cg = lg ^ (j&15)
    float M[64 * 64];        // [k][j]
    float aW1s[64 * 32];     // [k][j2]
    float t[64];
    float c[64];
    float aW2s[32];
    float ab1s[32];
    float scores[LPAD];
    float red[32];
    float pool4[256];
};

__global__ __launch_bounds__(256, 2) void attn_kernel(
    const int* __restrict__ user_id, const int* __restrict__ item_id,
    const int* __restrict__ item_category, const int* __restrict__ item_dur_bkt,
    const float* __restrict__ user_dense, const float* __restrict__ item_dense,
    const int* __restrict__ history_seq,
    const float* __restrict__ user_W, const float* __restrict__ item_W,
    const float* __restrict__ cat_W, const float* __restrict__ dur_W,
    const float* __restrict__ hist_W,
    const float* __restrict__ aW0, const float* __restrict__ ab0,
    const float* __restrict__ aW1, const float* __restrict__ ab1,
    const float* __restrict__ aW2, const float* __restrict__ ab2)
{
    extern __shared__ char smem_raw[];
    SmemA& S = *reinterpret_cast<SmemA*>(smem_raw);
    const int b = blockIdx.x;
    const int tid = threadIdx.x;
    const int lane = tid & 31;
    const int wid = tid >> 5;

    // ---- load t, weights, init scores ----
    if (tid < 64) S.t[tid] = item_W[item_id[b] * 64 + tid];
    for (int p = tid; p < 2048; p += 256) S.aW1s[p] = aW1[p];
    if (tid < 32) { S.aW2s[tid] = aW2[tid]; S.ab1s[tid] = ab1[tid]; }
    {
        float ab2v = ab2[0];
        for (int p = tid; p < LPAD; p += 256) S.scores[p] = ab2v;
    }
    __syncthreads();

    // ---- M[k][j] = aW0[k][j] + aW0[192+k][j] + t[k]*aW0[128+k][j] ----
    for (int idx = tid; idx < 4096; idx += 256) {
        int k = idx >> 6, j = idx & 63;
        S.M[idx] = aW0[idx] + aW0[(192 + k) * 64 + j] + S.t[k] * aW0[(128 + k) * 64 + j];
    }
    // ---- c[j] = ab0[j] + sum_k t[k]*(aW0[64+k][j] - aW0[192+k][j]) ----
    if (tid < 64) {
        float s = ab0[tid];
        #pragma unroll 8
        for (int k = 0; k < 64; k++)
            s += S.t[k] * (aW0[(64 + k) * 64 + tid] - aW0[(192 + k) * 64 + tid]);
        S.c[tid] = s;
    }
    // ---- gather history rows transposed; lane grid = 4 l x 8 k-pairs ----
    {
        int lsub = lane & 3, kp = lane >> 2;
        for (int i = wid * 4; i < LSEQ; i += 32) {
            int l = i + lsub;
            int row = history_seq[b * LSEQ + l];
            const float* rp = &hist_W[row * 64];
            #pragma unroll
            for (int cc = 0; cc < 4; cc++) {
                int k2 = (kp + 8 * cc) * 2;
                float2 v = *(const float2*)(rp + k2);
                S.histT[k2 * HSTR + l]       = v.x;
                S.histT[(k2 + 1) * HSTR + l] = v.y;
            }
        }
    }
    for (int p = tid; p < 64 * 8; p += 256)
        S.histT[(p >> 3) * HSTR + 200 + (p & 7)] = 0.f;
    __syncthreads();

    // ---- 4 chunks of 52 l ----
    const int lg = tid >> 4;          // 0..15 (active <13)
    const int jg = tid & 15;
    const int j0 = jg << 2;
    const int j0b = jg << 1;
    // participation mask for the lg<NLG branch, computed while converged
    const unsigned amask = __ballot_sync(0xffffffffu, lg < NLG);

    for (int c0 = 0; c0 < LPAD; c0 += CHUNK) {
        // GEMM1: h0[l][j] = relu(sum_k histT[k][l]*M[k][j] + c[j]); 4l x 4j
        if (lg < NLG) {
            int l0 = c0 + (lg << 2);
            u64t acc[2][4];
            #pragma unroll
            for (int jj = 0; jj < 4; jj++) {
                u64t cv = dup2(S.c[j0 + jj]);
                acc[0][jj] = cv; acc[1][jj] = cv;
            }
            const float* hptr = &S.histT[l0];
            const float* mptr = &S.M[j0];
            #pragma unroll 8
            for (int k = 0; k < 64; k++) {
                ulonglong2 av = *(const ulonglong2*)(hptr + k * HSTR);
                float4 bv = *(const float4*)(mptr + (k << 6));
                u64t b0d = dup2(bv.x), b1d = dup2(bv.y), b2d = dup2(bv.z), b3d = dup2(bv.w);
                fma2(acc[0][0], av.x, b0d); fma2(acc[1][0], av.y, b0d);
                fma2(acc[0][1], av.x, b1d); fma2(acc[1][1], av.y, b1d);
                fma2(acc[0][2], av.x, b2d); fma2(acc[1][2], av.y, b2d);
                fma2(acc[0][3], av.x, b3d); fma2(acc[1][3], av.y, b3d);
            }
            #pragma unroll
            for (int jj = 0; jj < 4; jj++) {
                int j = j0 + jj;
                int cg = lg ^ (j & 15);
                float v0, v1, v2, v3;
                unpack2(acc[0][jj], v0, v1);
                unpack2(acc[1][jj], v2, v3);
                *(float4*)&S.h0T[(j << 6) + (cg << 2)] =
                    make_float4(fmaxf(v0, 0.f), fmaxf(v1, 0.f), fmaxf(v2, 0.f), fmaxf(v3, 0.f));
            }
        }
        __syncthreads();

        // GEMM2 + score epilogue; 4l x 2j2 per thread, masked shfl-reduce over 16 jg
        if (lg < NLG) {
            u64t bi0 = dup2(S.ab1s[j0b]), bi1 = dup2(S.ab1s[j0b + 1]);
            u64t acc[2][2] = {{bi0, bi1}, {bi0, bi1}};
            #pragma unroll 8
            for (int k = 0; k < 64; k++) {
                int cg = lg ^ (k & 15);
                ulonglong2 av = *(const ulonglong2*)&S.h0T[(k << 6) + (cg << 2)];
                float2 wv = *(const float2*)&S.aW1s[(k << 5) + j0b];
                u64t w0d = dup2(wv.x), w1d = dup2(wv.y);
                fma2(acc[0][0], av.x, w0d); fma2(acc[1][0], av.y, w0d);
                fma2(acc[0][1], av.x, w1d); fma2(acc[1][1], av.y, w1d);
            }
            float w20 = S.aW2s[j0b], w21 = S.aW2s[j0b + 1];
            float sl[4];
            #pragma unroll
            for (int p = 0; p < 2; p++) {
                float h00, h01, h10, h11;
                unpack2(acc[p][0], h00, h01);
                unpack2(acc[p][1], h10, h11);
                sl[2 * p]     = fmaxf(h00, 0.f) * w20 + fmaxf(h10, 0.f) * w21;
                sl[2 * p + 1] = fmaxf(h01, 0.f) * w20 + fmaxf(h11, 0.f) * w21;
            }
            // reduce across the 16 jg lanes (butterfly stays within 16-lane halves)
            #pragma unroll
            for (int off = 1; off < 16; off <<= 1) {
                #pragma unroll
                for (int li = 0; li < 4; li++)
                    sl[li] += __shfl_xor_sync(amask, sl[li], off);
            }
            if (jg == 0) {
                int l0 = c0 + (lg << 2);
                #pragma unroll
                for (int li = 0; li < 4; li++)
                    S.scores[l0 + li] += sl[li];
            }
        }
        __syncthreads();
    }

    // ---- mask + softmax over L ----
    {
        float s = -3.402823466e38f;
        if (tid < LSEQ) {
            s = S.scores[tid];
            if (history_seq[b * LSEQ + tid] == 0) s = -1.0e9f;
        }
        float v = s;
        #pragma unroll
        for (int o = 16; o; o >>= 1) v = fmaxf(v, __shfl_xor_sync(0xffffffffu, v, o));
        if (lane == 0) S.red[wid] = v;
        __syncthreads();
        if (tid < 32) {
            float r = (tid < 8) ? S.red[tid] : -3.402823466e38f;
            #pragma unroll
            for (int o = 4; o; o >>= 1) r = fmaxf(r, __shfl_xor_sync(0xffffffffu, r, o));
            if (tid == 0) S.red[8] = r;
        }
        __syncthreads();
        float mx = S.red[8];
        float e = (tid < LSEQ) ? expf(s - mx) : 0.f;
        float v2 = e;
        #pragma unroll
        for (int o = 16; o; o >>= 1) v2 += __shfl_xor_sync(0xffffffffu, v2, o);
        if (lane == 0) S.red[wid] = v2;
        __syncthreads();
        if (tid < 32) {
            float r = (tid < 8) ? S.red[tid] : 0.f;
            #pragma unroll
            for (int o = 4; o; o >>= 1) r += __shfl_xor_sync(0xffffffffu, r, o);
            if (tid == 0) S.red[8] = r;
        }
        __syncthreads();
        float inv = 1.f / S.red[8];
        if (tid < LSEQ) S.scores[tid] = e * inv;
    }
    __syncthreads();

    // ---- pooled[k] = sum_l w[l]*histT[k][l] ----
    {
        int k = tid & 63, g = tid >> 6;
        float p = 0.f;
        for (int l = g; l < LSEQ; l += 4) p += S.histT[k * HSTR + l] * S.scores[l];
        S.pool4[(g << 6) + k] = p;
    }
    __syncthreads();
    if (tid < 64) {
        float pooled = S.pool4[tid] + S.pool4[64 + tid] + S.pool4[128 + tid] + S.pool4[192 + tid];
        g_xbuf[b * 244 + 180 + tid] = pooled;
    }
    // ---- assemble x ----
    if (tid < 64) {
        g_xbuf[b * 244 + tid] = user_W[user_id[b] * 64 + tid];
    } else if (tid < 128) {
        g_xbuf[b * 244 + tid] = S.t[tid - 64];
    } else if (tid < 144) {
        g_xbuf[b * 244 + tid] = cat_W[item_category[b] * 16 + (tid - 128)];
    } else if (tid < 152) {
        g_xbuf[b * 244 + tid] = dur_W[item_dur_bkt[b] * 8 + (tid - 144)];
    } else if (tid < 177) {
        g_xbuf[b * 244 + tid] = user_dense[b * 25 + (tid - 152)];
    } else if (tid < 180) {
        g_xbuf[b * 244 + tid] = item_dense[b * 3 + (tid - 177)];
    }
}

// ---- MLP: 8 samples/block, samples packed f32x2, batched weight loads for ILP ----
__global__ __launch_bounds__(256, 3) void mlp_kernel(
    const float* __restrict__ mW0, const float* __restrict__ mb0,
    const float* __restrict__ mW1, const float* __restrict__ mb1,
    const float* __restrict__ mW2, const float* __restrict__ mb2,
    float* __restrict__ out, int B)
{
    __shared__ __align__(16) float xsT[244 * 8];
    __shared__ __align__(16) float h0T[256 * 8];
    __shared__ __align__(16) float h1s[8 * 128];
    const int b0 = blockIdx.x * 8;
    const int tid = threadIdx.x;

    #pragma unroll
    for (int q = 0; q < 8; q++) {
        if (tid < 244 && (b0 + q) < B)
            xsT[tid * 8 + q] = g_xbuf[(b0 + q) * 244 + tid];
    }
    __syncthreads();

    // layer 0: 244 -> 256
    {
        u64t acc[4];
        u64t bias = dup2(mb0[tid]);
        #pragma unroll
        for (int p = 0; p < 4; p++) acc[p] = bias;
        #pragma unroll 1
        for (int i = 0; i < 240; i += 8) {
            float w[8];
            #pragma unroll
            for (int u = 0; u < 8; u++) w[u] = mW0[(i + u) * 256 + tid];
            #pragma unroll
            for (int u = 0; u < 8; u++) {
                u64t wd = dup2(w[u]);
                ulonglong2 x01 = *(const ulonglong2*)&xsT[(i + u) * 8];
                ulonglong2 x23 = *(const ulonglong2*)&xsT[(i + u) * 8 + 4];
                fma2(acc[0], x01.x, wd); fma2(acc[1], x01.y, wd);
                fma2(acc[2], x23.x, wd); fma2(acc[3], x23.y, wd);
            }
        }
        #pragma unroll
        for (int i = 240; i < 244; i++) {
            u64t wd = dup2(mW0[i * 256 + tid]);
            ulonglong2 x01 = *(const ulonglong2*)&xsT[i * 8];
            ulonglong2 x23 = *(const ulonglong2*)&xsT[i * 8 + 4];
            fma2(acc[0], x01.x, wd); fma2(acc[1], x01.y, wd);
            fma2(acc[2], x23.x, wd); fma2(acc[3], x23.y, wd);
        }
        #pragma unroll
        for (int p = 0; p < 4; p++) {
            float a, c;
            unpack2(acc[p], a, c);
            h0T[tid * 8 + 2 * p]     = fmaxf(a, 0.f);
            h0T[tid * 8 + 2 * p + 1] = fmaxf(c, 0.f);
        }
    }
    __syncthreads();

    // layer 1: 256 -> 128
    {
        int j = tid & 127, h = tid >> 7;
        u64t bias = dup2(mb1[j]);
        u64t acc[2] = {bias, bias};
        #pragma unroll 1
        for (int i = 0; i < 256; i += 8) {
            float w[8];
            #pragma unroll
            for (int u = 0; u < 8; u++) w[u] = mW1[(i + u) * 128 + j];
            #pragma unroll
            for (int u = 0; u < 8; u++) {
                u64t wd = dup2(w[u]);
                ulonglong2 a = *(const ulonglong2*)&h0T[(i + u) * 8 + h * 4];
                fma2(acc[0], a.x, wd); fma2(acc[1], a.y, wd);
            }
        }
        #pragma unroll
        for (int p = 0; p < 2; p++) {
            float a, c;
            unpack2(acc[p], a, c);
            h1s[(h * 4 + 2 * p) * 128 + j]     = fmaxf(a, 0.f);
            h1s[(h * 4 + 2 * p + 1) * 128 + j] = fmaxf(c, 0.f);
        }
    }
    __syncthreads();

    // layer 2: 128 -> 1, sigmoid; one warp per sample
    {
        int w = tid >> 5, lane = tid & 31;
        float m0 = mW2[lane], m1 = mW2[lane + 32], m2 = mW2[lane + 64], m3 = mW2[lane + 96];
        const float* hp = &h1s[w * 128];
        float v = hp[lane] * m0 + hp[lane + 32] * m1 + hp[lane + 64] * m2 + hp[lane + 96] * m3;
        #pragma unroll
        for (int o = 16; o; o >>= 1) v += __shfl_xor_sync(0xffffffffu, v, o);
        if (lane == 0 && (b0 + w) < B) {
            float logit = v + mb2[0];
            out[b0 + w] = 1.f / (1.f + expf(-logit));
        }
    }
}

extern "C" void kernel_launch(void* const* d_in, const int* in_sizes, int n_in,
                              void* d_out, int out_size)
{
    const int*   user_id       = (const int*)d_in[0];
    const int*   item_id       = (const int*)d_in[1];
    const int*   item_category = (const int*)d_in[2];
    const int*   item_dur_bkt  = (const int*)d_in[3];
    const float* user_dense    = (const float*)d_in[4];
    const float* item_dense    = (const float*)d_in[5];
    const int*   history_seq   = (const int*)d_in[6];
    const float* user_W        = (const float*)d_in[7];
    const float* item_W        = (const float*)d_in[8];
    const float* cat_W         = (const float*)d_in[9];
    const float* dur_W         = (const float*)d_in[10];
    const float* hist_W        = (const float*)d_in[11];
    const float* aW0 = (const float*)d_in[12];
    const float* ab0 = (const float*)d_in[13];
    const float* aW1 = (const float*)d_in[14];
    const float* ab1 = (const float*)d_in[15];
    const float* aW2 = (const float*)d_in[16];
    const float* ab2 = (const float*)d_in[17];
    const float* mW0 = (const float*)d_in[18];
    const float* mb0 = (const float*)d_in[19];
    const float* mW1 = (const float*)d_in[20];
    const float* mb1 = (const float*)d_in[21];
    const float* mW2 = (const float*)d_in[22];
    const float* mb2 = (const float*)d_in[23];

    const int B = in_sizes[0];
    float* out = (float*)d_out;

    cudaFuncSetAttribute(attn_kernel, cudaFuncAttributeMaxDynamicSharedMemorySize,
                         (int)sizeof(SmemA));

    attn_kernel<<<B, 256, sizeof(SmemA)>>>(
        user_id, item_id, item_category, item_dur_bkt,
        user_dense, item_dense, history_seq,
        user_W, item_W, cat_W, dur_W, hist_W,
        aW0, ab0, aW1, ab1, aW2, ab2);

    mlp_kernel<<<(B + 7) / 8, 256>>>(mW0, mb0, mW1, mb1, mW2, mb2, out, B);
}

// round 6
// speedup vs baseline: 2.2212x; 1.6292x over previous
#include <cuda_runtime.h>
#include <math.h>

#define LSEQ 200
#define HSTR 68      // histL row stride (floats): (4*gid+tig) banks, conflict-free A frags
#define MSTR 72      // M row stride: (8*tig+gid) banks, conflict-free B frags
#define W1STR 40     // aW1 row stride: (8*tig+gid) banks, conflict-free B frags
#define B_MAX 4096

__device__ float g_xbuf[B_MAX * 244];

typedef unsigned long long u64t;
typedef unsigned int u32t;

__device__ __forceinline__ u64t dup2(float x) {
    u64t r; asm("mov.b64 %0, {%1, %1};" : "=l"(r) : "f"(x)); return r;
}
__device__ __forceinline__ void fma2(u64t& d, u64t a, u64t b) {
    asm("fma.rn.f32x2 %0, %1, %2, %0;" : "+l"(d) : "l"(a), "l"(b));
}
__device__ __forceinline__ void unpack2(u64t v, float& a, float& b) {
    asm("mov.b64 {%0, %1}, %2;" : "=f"(a), "=f"(b) : "l"(v));
}
__device__ __forceinline__ u32t f2tf32(float f) {
    u32t u; asm("cvt.rna.tf32.f32 %0, %1;" : "=r"(u) : "f"(f)); return u;
}
__device__ __forceinline__ void mma_tf32(float& d0, float& d1, float& d2, float& d3,
                                         u32t a0, u32t a1, u32t a2, u32t a3,
                                         u32t b0, u32t b1) {
    asm volatile(
        "mma.sync.aligned.m16n8k8.row.col.f32.tf32.tf32.f32 "
        "{%0,%1,%2,%3},{%4,%5,%6,%7},{%8,%9},{%0,%1,%2,%3};"
        : "+f"(d0), "+f"(d1), "+f"(d2), "+f"(d3)
        : "r"(a0), "r"(a1), "r"(a2), "r"(a3), "r"(b0), "r"(b1));
}

struct __align__(16) SmemA {
    float histL[208 * HSTR];  // [l][k] fp32, rows 200..207 zero
    float M[64 * MSTR];       // [k][j]
    float aW1s[64 * W1STR];   // [k2][j2]
    float t[64];
    float c1[64];
    float ab1s[32];
    float aW2s[32];
    float scores[208];
    float red[32];
    float pool4[256];
};

__global__ __launch_bounds__(256, 2) void attn_kernel(
    const int* __restrict__ user_id, const int* __restrict__ item_id,
    const int* __restrict__ item_category, const int* __restrict__ item_dur_bkt,
    const float* __restrict__ user_dense, const float* __restrict__ item_dense,
    const int* __restrict__ history_seq,
    const float* __restrict__ user_W, const float* __restrict__ item_W,
    const float* __restrict__ cat_W, const float* __restrict__ dur_W,
    const float* __restrict__ hist_W,
    const float* __restrict__ aW0, const float* __restrict__ ab0,
    const float* __restrict__ aW1, const float* __restrict__ ab1,
    const float* __restrict__ aW2, const float* __restrict__ ab2)
{
    extern __shared__ char smem_raw[];
    SmemA& S = *reinterpret_cast<SmemA*>(smem_raw);
    const int b = blockIdx.x;
    const int tid = threadIdx.x;
    const int lane = tid & 31;
    const int w = tid >> 5;

    // ---- stage small weights ----
    if (tid < 64) S.t[tid] = item_W[item_id[b] * 64 + tid];
    for (int p = tid; p < 2048; p += 256) S.aW1s[(p >> 5) * W1STR + (p & 31)] = aW1[p];
    if (tid < 32) { S.aW2s[tid] = aW2[tid]; S.ab1s[tid] = ab1[tid]; }

    // ---- gather history rows (row-major, coalesced) ----
    {
        int c8 = tid & 7;
        for (int l = tid >> 3; l < LSEQ; l += 32) {
            int row = history_seq[b * LSEQ + l];
            const float4* rp = (const float4*)&hist_W[row * 64];
            float4 v0 = rp[c8 * 2], v1 = rp[c8 * 2 + 1];
            *(float4*)&S.histL[l * HSTR + c8 * 8]     = v0;
            *(float4*)&S.histL[l * HSTR + c8 * 8 + 4] = v1;
        }
    }
    // zero pad rows 200..207 (cols 0..63)
    for (int p = tid; p < 8 * 64; p += 256)
        S.histL[(LSEQ + (p >> 6)) * HSTR + (p & 63)] = 0.f;
    __syncthreads();

    // ---- M[k][j] = aW0[k][j] + aW0[192+k][j] + t[k]*aW0[128+k][j] ----
    for (int idx = tid; idx < 4096; idx += 256) {
        int k = idx >> 6, j = idx & 63;
        S.M[k * MSTR + j] = aW0[idx] + aW0[(192 + k) * 64 + j] + S.t[k] * aW0[(128 + k) * 64 + j];
    }
    // ---- c1[j] = ab0[j] + sum_k t[k]*(aW0[64+k][j] - aW0[192+k][j]) ----
    if (tid < 64) {
        float s = ab0[tid];
        #pragma unroll 8
        for (int k = 0; k < 64; k++)
            s += S.t[k] * (aW0[(64 + k) * 64 + tid] - aW0[(192 + k) * 64 + tid]);
        S.c1[tid] = s;
    }
    __syncthreads();

    // ---- tensor-core attention: warp w owns l-tiles {w, w+8} ----
    const int gid = lane >> 2;   // 0..7
    const int tig = lane & 3;    // 0..3
    const bool odd = tig & 1;
    const int src0 = gid * 4 + (tig >> 1);
    const int src2 = src0 + 2;
    const float ab2v = ab2[0];

    for (int lt = w; lt < 13; lt += 8) {
        const int l0 = lt * 16;

        // GEMM1: C1[16 x 64] = hist[16 x 64k] * M[64k x 64j]
        float C1[8][4] = {};
        #pragma unroll
        for (int kt = 0; kt < 8; kt++) {
            const float* ap = &S.histL[(l0 + gid) * HSTR + kt * 8 + tig];
            u32t ua0 = f2tf32(ap[0]);
            u32t ua1 = f2tf32(ap[8 * HSTR]);
            u32t ua2 = f2tf32(ap[4]);
            u32t ua3 = f2tf32(ap[8 * HSTR + 4]);
            const float* bp = &S.M[(kt * 8 + tig) * MSTR + gid];
            #pragma unroll
            for (int jt = 0; jt < 8; jt++) {
                u32t ub0 = f2tf32(bp[jt * 8]);
                u32t ub1 = f2tf32(bp[4 * MSTR + jt * 8]);
                mma_tf32(C1[jt][0], C1[jt][1], C1[jt][2], C1[jt][3],
                         ua0, ua1, ua2, ua3, ub0, ub1);
            }
        }
        // bias + relu (h0 stays in registers)
        #pragma unroll
        for (int jt = 0; jt < 8; jt++) {
            float cb0 = S.c1[jt * 8 + 2 * tig], cb1 = S.c1[jt * 8 + 2 * tig + 1];
            C1[jt][0] = fmaxf(C1[jt][0] + cb0, 0.f);
            C1[jt][1] = fmaxf(C1[jt][1] + cb1, 0.f);
            C1[jt][2] = fmaxf(C1[jt][2] + cb0, 0.f);
            C1[jt][3] = fmaxf(C1[jt][3] + cb1, 0.f);
        }

        // GEMM2: C2[16 x 32] = h0[16 x 64] * aW1[64 x 32]; A frags via shfl from C1
        float C2[4][4] = {};
        #pragma unroll
        for (int kt = 0; kt < 8; kt++) {
            float v00 = __shfl_sync(0xffffffffu, C1[kt][0], src0);
            float v01 = __shfl_sync(0xffffffffu, C1[kt][1], src0);
            float v10 = __shfl_sync(0xffffffffu, C1[kt][2], src0);
            float v11 = __shfl_sync(0xffffffffu, C1[kt][3], src0);
            float v20 = __shfl_sync(0xffffffffu, C1[kt][0], src2);
            float v21 = __shfl_sync(0xffffffffu, C1[kt][1], src2);
            float v30 = __shfl_sync(0xffffffffu, C1[kt][2], src2);
            float v31 = __shfl_sync(0xffffffffu, C1[kt][3], src2);
            u32t ua0 = f2tf32(odd ? v01 : v00);
            u32t ua1 = f2tf32(odd ? v11 : v10);
            u32t ua2 = f2tf32(odd ? v21 : v20);
            u32t ua3 = f2tf32(odd ? v31 : v30);
            const float* bp = &S.aW1s[(kt * 8 + tig) * W1STR + gid];
            #pragma unroll
            for (int jt = 0; jt < 4; jt++) {
                u32t ub0 = f2tf32(bp[jt * 8]);
                u32t ub1 = f2tf32(bp[4 * W1STR + jt * 8]);
                mma_tf32(C2[jt][0], C2[jt][1], C2[jt][2], C2[jt][3],
                         ua0, ua1, ua2, ua3, ub0, ub1);
            }
        }
        // scores epilogue: relu(h1 + ab1) . aW2, reduce over the 4 tig lanes
        float sr = 0.f, sr8 = 0.f;
        #pragma unroll
        for (int jt = 0; jt < 4; jt++) {
            int j = jt * 8 + 2 * tig;
            float b0v = S.ab1s[j], b1v = S.ab1s[j + 1];
            float w0v = S.aW2s[j], w1v = S.aW2s[j + 1];
            sr  += fmaxf(C2[jt][0] + b0v, 0.f) * w0v + fmaxf(C2[jt][1] + b1v, 0.f) * w1v;
            sr8 += fmaxf(C2[jt][2] + b0v, 0.f) * w0v + fmaxf(C2[jt][3] + b1v, 0.f) * w1v;
        }
        sr  += __shfl_xor_sync(0xffffffffu, sr, 1);
        sr  += __shfl_xor_sync(0xffffffffu, sr, 2);
        sr8 += __shfl_xor_sync(0xffffffffu, sr8, 1);
        sr8 += __shfl_xor_sync(0xffffffffu, sr8, 2);
        if (tig == 0) {
            S.scores[l0 + gid]     = sr + ab2v;
            S.scores[l0 + gid + 8] = sr8 + ab2v;
        }
    }
    __syncthreads();

    // ---- mask + softmax over L ----
    {
        float s = -3.402823466e38f;
        if (tid < LSEQ) {
            s = S.scores[tid];
            if (history_seq[b * LSEQ + tid] == 0) s = -1.0e9f;
        }
        float v = s;
        #pragma unroll
        for (int o = 16; o; o >>= 1) v = fmaxf(v, __shfl_xor_sync(0xffffffffu, v, o));
        if (lane == 0) S.red[w] = v;
        __syncthreads();
        if (tid < 32) {
            float r = (tid < 8) ? S.red[tid] : -3.402823466e38f;
            #pragma unroll
            for (int o = 4; o; o >>= 1) r = fmaxf(r, __shfl_xor_sync(0xffffffffu, r, o));
            if (tid == 0) S.red[8] = r;
        }
        __syncthreads();
        float mx = S.red[8];
        float e = (tid < LSEQ) ? expf(s - mx) : 0.f;
        float v2 = e;
        #pragma unroll
        for (int o = 16; o; o >>= 1) v2 += __shfl_xor_sync(0xffffffffu, v2, o);
        if (lane == 0) S.red[w] = v2;
        __syncthreads();
        if (tid < 32) {
            float r = (tid < 8) ? S.red[tid] : 0.f;
            #pragma unroll
            for (int o = 4; o; o >>= 1) r += __shfl_xor_sync(0xffffffffu, r, o);
            if (tid == 0) S.red[8] = r;
        }
        __syncthreads();
        float inv = 1.f / S.red[8];
        if (tid < LSEQ) S.scores[tid] = e * inv;
    }
    __syncthreads();

    // ---- pooled[k] = sum_l w[l]*hist[l][k] (fp32 exact) ----
    {
        int k = tid & 63, g = tid >> 6;
        float p = 0.f;
        for (int l = g; l < LSEQ; l += 4) p += S.histL[l * HSTR + k] * S.scores[l];
        S.pool4[(g << 6) + k] = p;
    }
    __syncthreads();
    if (tid < 64) {
        float pooled = S.pool4[tid] + S.pool4[64 + tid] + S.pool4[128 + tid] + S.pool4[192 + tid];
        g_xbuf[b * 244 + 180 + tid] = pooled;
    }
    // ---- assemble x ----
    if (tid < 64) {
        g_xbuf[b * 244 + tid] = user_W[user_id[b] * 64 + tid];
    } else if (tid < 128) {
        g_xbuf[b * 244 + tid] = S.t[tid - 64];
    } else if (tid < 144) {
        g_xbuf[b * 244 + tid] = cat_W[item_category[b] * 16 + (tid - 128)];
    } else if (tid < 152) {
        g_xbuf[b * 244 + tid] = dur_W[item_dur_bkt[b] * 8 + (tid - 144)];
    } else if (tid < 177) {
        g_xbuf[b * 244 + tid] = user_dense[b * 25 + (tid - 152)];
    } else if (tid < 180) {
        g_xbuf[b * 244 + tid] = item_dense[b * 3 + (tid - 177)];
    }
}

// ---- MLP: 8 samples/block, samples packed f32x2, batched weight loads ----
__global__ __launch_bounds__(256, 3) void mlp_kernel(
    const float* __restrict__ mW0, const float* __restrict__ mb0,
    const float* __restrict__ mW1, const float* __restrict__ mb1,
    const float* __restrict__ mW2, const float* __restrict__ mb2,
    float* __restrict__ out, int B)
{
    __shared__ __align__(16) float xsT[244 * 8];
    __shared__ __align__(16) float h0T[256 * 8];
    __shared__ __align__(16) float h1s[8 * 128];
    const int b0 = blockIdx.x * 8;
    const int tid = threadIdx.x;

    #pragma unroll
    for (int q = 0; q < 8; q++) {
        if (tid < 244 && (b0 + q) < B)
            xsT[tid * 8 + q] = g_xbuf[(b0 + q) * 244 + tid];
    }
    __syncthreads();

    {
        u64t acc[4];
        u64t bias = dup2(mb0[tid]);
        #pragma unroll
        for (int p = 0; p < 4; p++) acc[p] = bias;
        #pragma unroll 1
        for (int i = 0; i < 240; i += 8) {
            float wv[8];
            #pragma unroll
            for (int u = 0; u < 8; u++) wv[u] = mW0[(i + u) * 256 + tid];
            #pragma unroll
            for (int u = 0; u < 8; u++) {
                u64t wd = dup2(wv[u]);
                ulonglong2 x01 = *(const ulonglong2*)&xsT[(i + u) * 8];
                ulonglong2 x23 = *(const ulonglong2*)&xsT[(i + u) * 8 + 4];
                fma2(acc[0], x01.x, wd); fma2(acc[1], x01.y, wd);
                fma2(acc[2], x23.x, wd); fma2(acc[3], x23.y, wd);
            }
        }
        #pragma unroll
        for (int i = 240; i < 244; i++) {
            u64t wd = dup2(mW0[i * 256 + tid]);
            ulonglong2 x01 = *(const ulonglong2*)&xsT[i * 8];
            ulonglong2 x23 = *(const ulonglong2*)&xsT[i * 8 + 4];
            fma2(acc[0], x01.x, wd); fma2(acc[1], x01.y, wd);
            fma2(acc[2], x23.x, wd); fma2(acc[3], x23.y, wd);
        }
        #pragma unroll
        for (int p = 0; p < 4; p++) {
            float a, c;
            unpack2(acc[p], a, c);
            h0T[tid * 8 + 2 * p]     = fmaxf(a, 0.f);
            h0T[tid * 8 + 2 * p + 1] = fmaxf(c, 0.f);
        }
    }
    __syncthreads();

    {
        int j = tid & 127, h = tid >> 7;
        u64t bias = dup2(mb1[j]);
        u64t acc[2] = {bias, bias};
        #pragma unroll 1
        for (int i = 0; i < 256; i += 8) {
            float wv[8];
            #pragma unroll
            for (int u = 0; u < 8; u++) wv[u] = mW1[(i + u) * 128 + j];
            #pragma unroll
            for (int u = 0; u < 8; u++) {
                u64t wd = dup2(wv[u]);
                ulonglong2 a = *(const ulonglong2*)&h0T[(i + u) * 8 + h * 4];
                fma2(acc[0], a.x, wd); fma2(acc[1], a.y, wd);
            }
        }
        #pragma unroll
        for (int p = 0; p < 2; p++) {
            float a, c;
            unpack2(acc[p], a, c);
            h1s[(h * 4 + 2 * p) * 128 + j]     = fmaxf(a, 0.f);
            h1s[(h * 4 + 2 * p + 1) * 128 + j] = fmaxf(c, 0.f);
        }
    }
    __syncthreads();

    {
        int wsel = tid >> 5, lane = tid & 31;
        float m0 = mW2[lane], m1 = mW2[lane + 32], m2 = mW2[lane + 64], m3 = mW2[lane + 96];
        const float* hp = &h1s[wsel * 128];
        float v = hp[lane] * m0 + hp[lane + 32] * m1 + hp[lane + 64] * m2 + hp[lane + 96] * m3;
        #pragma unroll
        for (int o = 16; o; o >>= 1) v += __shfl_xor_sync(0xffffffffu, v, o);
        if (lane == 0 && (b0 + wsel) < B) {
            float logit = v + mb2[0];
            out[b0 + wsel] = 1.f / (1.f + expf(-logit));
        }
    }
}

extern "C" void kernel_launch(void* const* d_in, const int* in_sizes, int n_in,
                              void* d_out, int out_size)
{
    const int*   user_id       = (const int*)d_in[0];
    const int*   item_id       = (const int*)d_in[1];
    const int*   item_category = (const int*)d_in[2];
    const int*   item_dur_bkt  = (const int*)d_in[3];
    const float* user_dense    = (const float*)d_in[4];
    const float* item_dense    = (const float*)d_in[5];
    const int*   history_seq   = (const int*)d_in[6];
    const float* user_W        = (const float*)d_in[7];
    const float* item_W        = (const float*)d_in[8];
    const float* cat_W         = (const float*)d_in[9];
    const float* dur_W         = (const float*)d_in[10];
    const float* hist_W        = (const float*)d_in[11];
    const float* aW0 = (const float*)d_in[12];
    const float* ab0 = (const float*)d_in[13];
    const float* aW1 = (const float*)d_in[14];
    const float* ab1 = (const float*)d_in[15];
    const float* aW2 = (const float*)d_in[16];
    const float* ab2 = (const float*)d_in[17];
    const float* mW0 = (const float*)d_in[18];
    const float* mb0 = (const float*)d_in[19];
    const float* mW1 = (const float*)d_in[20];
    const float* mb1 = (const float*)d_in[21];
    const float* mW2 = (const float*)d_in[22];
    const float* mb2 = (const float*)d_in[23];

    const int B = in_sizes[0];
    float* out = (float*)d_out;

    cudaFuncSetAttribute(attn_kernel, cudaFuncAttributeMaxDynamicSharedMemorySize,
                         (int)sizeof(SmemA));

    attn_kernel<<<B, 256, sizeof(SmemA)>>>(
        user_id, item_id, item_category, item_dur_bkt,
        user_dense, item_dense, history_seq,
        user_W, item_W, cat_W, dur_W, hist_W,
        aW0, ab0, aW1, ab1, aW2, ab2);

    mlp_kernel<<<(B + 7) / 8, 256>>>(mW0, mb0, mW1, mb1, mW2, mb2, out, B);
}

// round 7
// speedup vs baseline: 2.5215x; 1.1352x over previous
#include <cuda_runtime.h>
#include <math.h>

#define LSEQ 200
#define HSTR 68      // histL row stride (floats)
#define MP_STR 68    // Mp row stride (uint2) per (kt,tig) row
#define W1P_STR 36   // aW1p row stride (uint2)
#define B_MAX 4096

__device__ float g_xbuf[B_MAX * 244];

typedef unsigned long long u64t;
typedef unsigned int u32t;

__device__ __forceinline__ u64t dup2(float x) {
    u64t r; asm("mov.b64 %0, {%1, %1};" : "=l"(r) : "f"(x)); return r;
}
__device__ __forceinline__ void fma2(u64t& d, u64t a, u64t b) {
    asm("fma.rn.f32x2 %0, %1, %2, %0;" : "+l"(d) : "l"(a), "l"(b));
}
__device__ __forceinline__ void unpack2(u64t v, float& a, float& b) {
    asm("mov.b64 {%0, %1}, %2;" : "=f"(a), "=f"(b) : "l"(v));
}
__device__ __forceinline__ u32t f2tf32(float f) {
    u32t u; asm("cvt.rna.tf32.f32 %0, %1;" : "=r"(u) : "f"(f)); return u;
}
__device__ __forceinline__ void mma_tf32(float& d0, float& d1, float& d2, float& d3,
                                         u32t a0, u32t a1, u32t a2, u32t a3,
                                         u32t b0, u32t b1) {
    asm volatile(
        "mma.sync.aligned.m16n8k8.row.col.f32.tf32.tf32.f32 "
        "{%0,%1,%2,%3},{%4,%5,%6,%7},{%8,%9},{%0,%1,%2,%3};"
        : "+f"(d0), "+f"(d1), "+f"(d2), "+f"(d3)
        : "r"(a0), "r"(a1), "r"(a2), "r"(a3), "r"(b0), "r"(b1));
}

struct __align__(16) SmemA {
    float histL[208 * HSTR];     // [l][k] fp32, rows 200..207 zero
    uint2 Mp[32 * MP_STR];       // [(kt*4+tig)*68 + j] = {tf32 M[kt*8+tig][j], tf32 M[kt*8+tig+4][j]}
    uint2 aW1p[32 * W1P_STR];    // [(kt*4+tig)*36 + j] = {tf32 aW1[kt*8+tig][j], tf32 aW1[kt*8+tig+4][j]}
    float t[64];
    float c1[64];
    float ab1s[32];
    float aW2s[32];
    float scores[208];
    float red[32];
    float pool4[256];
};

__global__ __launch_bounds__(256, 2) void attn_kernel(
    const int* __restrict__ user_id, const int* __restrict__ item_id,
    const int* __restrict__ item_category, const int* __restrict__ item_dur_bkt,
    const float* __restrict__ user_dense, const float* __restrict__ item_dense,
    const int* __restrict__ history_seq,
    const float* __restrict__ user_W, const float* __restrict__ item_W,
    const float* __restrict__ cat_W, const float* __restrict__ dur_W,
    const float* __restrict__ hist_W,
    const float* __restrict__ aW0, const float* __restrict__ ab0,
    const float* __restrict__ aW1, const float* __restrict__ ab1,
    const float* __restrict__ aW2, const float* __restrict__ ab2)
{
    extern __shared__ char smem_raw[];
    SmemA& S = *reinterpret_cast<SmemA*>(smem_raw);
    float* Mpf = (float*)S.Mp;
    float* W1pf = (float*)S.aW1p;
    const int b = blockIdx.x;
    const int tid = threadIdx.x;
    const int lane = tid & 31;
    const int w = tid >> 5;

    // ---- phase A: t, aW1p (tf32 packed), small vectors, gather ----
    if (tid < 64) S.t[tid] = item_W[item_id[b] * 64 + tid];
    for (int p = tid; p < 2048; p += 256) {
        int k = p >> 5, j = p & 31;
        int kt = k >> 3, r = k & 7, tg = r & 3, half = r >> 2;
        W1pf[(((kt * 4 + tg) * W1P_STR) + j) * 2 + half] = __uint_as_float(f2tf32(aW1[p]));
    }
    if (tid < 32) { S.aW2s[tid] = aW2[tid]; S.ab1s[tid] = ab1[tid]; }
    {
        int c8 = tid & 7;
        for (int l = tid >> 3; l < LSEQ; l += 32) {
            int row = history_seq[b * LSEQ + l];
            const float4* rp = (const float4*)&hist_W[row * 64];
            float4 v0 = rp[c8 * 2], v1 = rp[c8 * 2 + 1];
            *(float4*)&S.histL[l * HSTR + c8 * 8]     = v0;
            *(float4*)&S.histL[l * HSTR + c8 * 8 + 4] = v1;
        }
    }
    for (int p = tid; p < 8 * 64; p += 256)
        S.histL[(LSEQ + (p >> 6)) * HSTR + (p & 63)] = 0.f;
    __syncthreads();

    // ---- phase B: Mp (tf32 packed) + c1 partials ----
    for (int idx = tid; idx < 4096; idx += 256) {
        int k = idx >> 6, j = idx & 63;
        float v = aW0[idx] + aW0[(192 + k) * 64 + j] + S.t[k] * aW0[(128 + k) * 64 + j];
        int kt = k >> 3, r = k & 7, tg = r & 3, half = r >> 2;
        Mpf[(((kt * 4 + tg) * MP_STR) + j) * 2 + half] = __uint_as_float(f2tf32(v));
    }
    {
        int j = tid & 63, kq = tid >> 6;
        float s = 0.f;
        #pragma unroll 4
        for (int k = kq * 16; k < kq * 16 + 16; k++)
            s += S.t[k] * (aW0[(64 + k) * 64 + j] - aW0[(192 + k) * 64 + j]);
        S.pool4[tid] = s;
    }
    __syncthreads();
    if (tid < 64)
        S.c1[tid] = ab0[tid] + S.pool4[tid] + S.pool4[64 + tid]
                  + S.pool4[128 + tid] + S.pool4[192 + tid];
    __syncthreads();

    // ---- tensor-core attention: warp w owns l-tiles {w, w+8} ----
    const int gid = lane >> 2;   // 0..7
    const int tig = lane & 3;    // 0..3
    const bool odd = tig & 1;
    const int src0 = gid * 4 + (tig >> 1);
    const int src2 = src0 + 2;
    const float ab2v = ab2[0];

    for (int lt = w; lt < 13; lt += 8) {
        const int l0 = lt * 16;

        // GEMM1: C1[16 x 64] = hist[16 x 64] * M[64 x 64]
        float C1[8][4] = {};
        #pragma unroll
        for (int kt = 0; kt < 8; kt++) {
            const float* ap = &S.histL[(l0 + gid) * HSTR + kt * 8 + tig];
            u32t ua0 = f2tf32(ap[0]);
            u32t ua1 = f2tf32(ap[8 * HSTR]);
            u32t ua2 = f2tf32(ap[4]);
            u32t ua3 = f2tf32(ap[8 * HSTR + 4]);
            const uint2* bp = &S.Mp[(kt * 4 + tig) * MP_STR + gid];
            #pragma unroll
            for (int jt = 0; jt < 8; jt++) {
                uint2 bb = bp[jt * 8];
                mma_tf32(C1[jt][0], C1[jt][1], C1[jt][2], C1[jt][3],
                         ua0, ua1, ua2, ua3, bb.x, bb.y);
            }
        }
        // bias + relu (h0 stays in registers)
        #pragma unroll
        for (int jt = 0; jt < 8; jt++) {
            float cb0 = S.c1[jt * 8 + 2 * tig], cb1 = S.c1[jt * 8 + 2 * tig + 1];
            C1[jt][0] = fmaxf(C1[jt][0] + cb0, 0.f);
            C1[jt][1] = fmaxf(C1[jt][1] + cb1, 0.f);
            C1[jt][2] = fmaxf(C1[jt][2] + cb0, 0.f);
            C1[jt][3] = fmaxf(C1[jt][3] + cb1, 0.f);
        }

        // GEMM2: C2[16 x 32] = h0[16 x 64] * aW1[64 x 32]; A frags via shfl from C1
        float C2[4][4] = {};
        #pragma unroll
        for (int kt = 0; kt < 8; kt++) {
            float v00 = __shfl_sync(0xffffffffu, C1[kt][0], src0);
            float v01 = __shfl_sync(0xffffffffu, C1[kt][1], src0);
            float v10 = __shfl_sync(0xffffffffu, C1[kt][2], src0);
            float v11 = __shfl_sync(0xffffffffu, C1[kt][3], src0);
            float v20 = __shfl_sync(0xffffffffu, C1[kt][0], src2);
            float v21 = __shfl_sync(0xffffffffu, C1[kt][1], src2);
            float v30 = __shfl_sync(0xffffffffu, C1[kt][2], src2);
            float v31 = __shfl_sync(0xffffffffu, C1[kt][3], src2);
            u32t ua0 = f2tf32(odd ? v01 : v00);
            u32t ua1 = f2tf32(odd ? v11 : v10);
            u32t ua2 = f2tf32(odd ? v21 : v20);
            u32t ua3 = f2tf32(odd ? v31 : v30);
            const uint2* bp = &S.aW1p[(kt * 4 + tig) * W1P_STR + gid];
            #pragma unroll
            for (int jt = 0; jt < 4; jt++) {
                uint2 bb = bp[jt * 8];
                mma_tf32(C2[jt][0], C2[jt][1], C2[jt][2], C2[jt][3],
                         ua0, ua1, ua2, ua3, bb.x, bb.y);
            }
        }
        // scores: relu(h1 + ab1) . aW2, reduce over the 4 tig lanes
        float sr = 0.f, sr8 = 0.f;
        #pragma unroll
        for (int jt = 0; jt < 4; jt++) {
            int j = jt * 8 + 2 * tig;
            float b0v = S.ab1s[j], b1v = S.ab1s[j + 1];
            float w0v = S.aW2s[j], w1v = S.aW2s[j + 1];
            sr  += fmaxf(C2[jt][0] + b0v, 0.f) * w0v + fmaxf(C2[jt][1] + b1v, 0.f) * w1v;
            sr8 += fmaxf(C2[jt][2] + b0v, 0.f) * w0v + fmaxf(C2[jt][3] + b1v, 0.f) * w1v;
        }
        sr  += __shfl_xor_sync(0xffffffffu, sr, 1);
        sr  += __shfl_xor_sync(0xffffffffu, sr, 2);
        sr8 += __shfl_xor_sync(0xffffffffu, sr8, 1);
        sr8 += __shfl_xor_sync(0xffffffffu, sr8, 2);
        if (tig == 0) {
            S.scores[l0 + gid]     = sr + ab2v;
            S.scores[l0 + gid + 8] = sr8 + ab2v;
        }
    }
    __syncthreads();

    // ---- mask + softmax over L ----
    {
        float s = -3.402823466e38f;
        if (tid < LSEQ) {
            s = S.scores[tid];
            if (history_seq[b * LSEQ + tid] == 0) s = -1.0e9f;
        }
        float v = s;
        #pragma unroll
        for (int o = 16; o; o >>= 1) v = fmaxf(v, __shfl_xor_sync(0xffffffffu, v, o));
        if (lane == 0) S.red[w] = v;
        __syncthreads();
        if (tid < 32) {
            float r = (tid < 8) ? S.red[tid] : -3.402823466e38f;
            #pragma unroll
            for (int o = 4; o; o >>= 1) r = fmaxf(r, __shfl_xor_sync(0xffffffffu, r, o));
            if (tid == 0) S.red[8] = r;
        }
        __syncthreads();
        float mx = S.red[8];
        float e = (tid < LSEQ) ? expf(s - mx) : 0.f;
        float v2 = e;
        #pragma unroll
        for (int o = 16; o; o >>= 1) v2 += __shfl_xor_sync(0xffffffffu, v2, o);
        if (lane == 0) S.red[w] = v2;
        __syncthreads();
        if (tid < 32) {
            float r = (tid < 8) ? S.red[tid] : 0.f;
            #pragma unroll
            for (int o = 4; o; o >>= 1) r += __shfl_xor_sync(0xffffffffu, r, o);
            if (tid == 0) S.red[8] = r;
        }
        __syncthreads();
        float inv = 1.f / S.red[8];
        if (tid < LSEQ) S.scores[tid] = e * inv;
    }
    __syncthreads();

    // ---- pooled[k] = sum_l w[l]*hist[l][k] (fp32 exact) ----
    {
        int k = tid & 63, g = tid >> 6;
        float p = 0.f;
        for (int l = g; l < LSEQ; l += 4) p += S.histL[l * HSTR + k] * S.scores[l];
        S.pool4[(g << 6) + k] = p;
    }
    __syncthreads();
    if (tid < 64) {
        float pooled = S.pool4[tid] + S.pool4[64 + tid] + S.pool4[128 + tid] + S.pool4[192 + tid];
        g_xbuf[b * 244 + 180 + tid] = pooled;
    }
    // ---- assemble x ----
    if (tid < 64) {
        g_xbuf[b * 244 + tid] = user_W[user_id[b] * 64 + tid];
    } else if (tid < 128) {
        g_xbuf[b * 244 + tid] = S.t[tid - 64];
    } else if (tid < 144) {
        g_xbuf[b * 244 + tid] = cat_W[item_category[b] * 16 + (tid - 128)];
    } else if (tid < 152) {
        g_xbuf[b * 244 + tid] = dur_W[item_dur_bkt[b] * 8 + (tid - 144)];
    } else if (tid < 177) {
        g_xbuf[b * 244 + tid] = user_dense[b * 25 + (tid - 152)];
    } else if (tid < 180) {
        g_xbuf[b * 244 + tid] = item_dense[b * 3 + (tid - 177)];
    }
}

// ---- MLP: 16 samples/block as two 8-sample groups, f32x2 packed ----
__global__ __launch_bounds__(256, 2) void mlp_kernel(
    const float* __restrict__ mW0, const float* __restrict__ mb0,
    const float* __restrict__ mW1, const float* __restrict__ mb1,
    const float* __restrict__ mW2, const float* __restrict__ mb2,
    float* __restrict__ out, int B)
{
    __shared__ __align__(16) float xsA[244 * 8];
    __shared__ __align__(16) float xsB[244 * 8];
    __shared__ __align__(16) float h0A[256 * 8];
    __shared__ __align__(16) float h0B[256 * 8];
    __shared__ __align__(16) float h1s[16 * 128];
    const int b0 = blockIdx.x * 16;
    const int tid = threadIdx.x;

    #pragma unroll
    for (int q = 0; q < 8; q++) {
        if (tid < 244) {
            if (b0 + q < B)     xsA[tid * 8 + q] = g_xbuf[(b0 + q) * 244 + tid];
            if (b0 + 8 + q < B) xsB[tid * 8 + q] = g_xbuf[(b0 + 8 + q) * 244 + tid];
        }
    }
    __syncthreads();

    // layer 0: 244 -> 256, 16 samples (8 fma2 per weight load)
    {
        u64t acc[8];
        u64t bias = dup2(mb0[tid]);
        #pragma unroll
        for (int p = 0; p < 8; p++) acc[p] = bias;
        #pragma unroll 1
        for (int i = 0; i < 240; i += 8) {
            float wv[8];
            #pragma unroll
            for (int u = 0; u < 8; u++) wv[u] = mW0[(i + u) * 256 + tid];
            #pragma unroll
            for (int u = 0; u < 8; u++) {
                u64t wd = dup2(wv[u]);
                ulonglong2 a01 = *(const ulonglong2*)&xsA[(i + u) * 8];
                ulonglong2 a23 = *(const ulonglong2*)&xsA[(i + u) * 8 + 4];
                ulonglong2 b01 = *(const ulonglong2*)&xsB[(i + u) * 8];
                ulonglong2 b23 = *(const ulonglong2*)&xsB[(i + u) * 8 + 4];
                fma2(acc[0], a01.x, wd); fma2(acc[1], a01.y, wd);
                fma2(acc[2], a23.x, wd); fma2(acc[3], a23.y, wd);
                fma2(acc[4], b01.x, wd); fma2(acc[5], b01.y, wd);
                fma2(acc[6], b23.x, wd); fma2(acc[7], b23.y, wd);
            }
        }
        #pragma unroll
        for (int i = 240; i < 244; i++) {
            u64t wd = dup2(mW0[i * 256 + tid]);
            ulonglong2 a01 = *(const ulonglong2*)&xsA[i * 8];
            ulonglong2 a23 = *(const ulonglong2*)&xsA[i * 8 + 4];
            ulonglong2 b01 = *(const ulonglong2*)&xsB[i * 8];
            ulonglong2 b23 = *(const ulonglong2*)&xsB[i * 8 + 4];
            fma2(acc[0], a01.x, wd); fma2(acc[1], a01.y, wd);
            fma2(acc[2], a23.x, wd); fma2(acc[3], a23.y, wd);
            fma2(acc[4], b01.x, wd); fma2(acc[5], b01.y, wd);
            fma2(acc[6], b23.x, wd); fma2(acc[7], b23.y, wd);
        }
        #pragma unroll
        for (int p = 0; p < 4; p++) {
            float a, c;
            unpack2(acc[p], a, c);
            h0A[tid * 8 + 2 * p]     = fmaxf(a, 0.f);
            h0A[tid * 8 + 2 * p + 1] = fmaxf(c, 0.f);
            unpack2(acc[4 + p], a, c);
            h0B[tid * 8 + 2 * p]     = fmaxf(a, 0.f);
            h0B[tid * 8 + 2 * p + 1] = fmaxf(c, 0.f);
        }
    }
    __syncthreads();

    // layer 1: 256 -> 128; half h handles group A or B (8 samples)
    {
        int j = tid & 127, h = tid >> 7;
        const float* h0p = h ? h0B : h0A;
        u64t bias = dup2(mb1[j]);
        u64t acc[4] = {bias, bias, bias, bias};
        #pragma unroll 1
        for (int i = 0; i < 256; i += 8) {
            float wv[8];
            #pragma unroll
            for (int u = 0; u < 8; u++) wv[u] = mW1[(i + u) * 128 + j];
            #pragma unroll
            for (int u = 0; u < 8; u++) {
                u64t wd = dup2(wv[u]);
                ulonglong2 a01 = *(const ulonglong2*)&h0p[(i + u) * 8];
                ulonglong2 a23 = *(const ulonglong2*)&h0p[(i + u) * 8 + 4];
                fma2(acc[0], a01.x, wd); fma2(acc[1], a01.y, wd);
                fma2(acc[2], a23.x, wd); fma2(acc[3], a23.y, wd);
            }
        }
        #pragma unroll
        for (int p = 0; p < 4; p++) {
            float a, c;
            unpack2(acc[p], a, c);
            h1s[(h * 8 + 2 * p) * 128 + j]     = fmaxf(a, 0.f);
            h1s[(h * 8 + 2 * p + 1) * 128 + j] = fmaxf(c, 0.f);
        }
    }
    __syncthreads();

    // layer 2: 128 -> 1, sigmoid; warp w handles samples w and w+8
    {
        int wsel = tid >> 5, lane = tid & 31;
        float m0 = mW2[lane], m1 = mW2[lane + 32], m2 = mW2[lane + 64], m3 = mW2[lane + 96];
        #pragma unroll
        for (int g = 0; g < 2; g++) {
            int s = wsel + g * 8;
            const float* hp = &h1s[s * 128];
            float v = hp[lane] * m0 + hp[lane + 32] * m1 + hp[lane + 64] * m2 + hp[lane + 96] * m3;
            #pragma unroll
            for (int o = 16; o; o >>= 1) v += __shfl_xor_sync(0xffffffffu, v, o);
            if (lane == 0 && (b0 + s) < B) {
                float logit = v + mb2[0];
                out[b0 + s] = 1.f / (1.f + expf(-logit));
            }
        }
    }
}

extern "C" void kernel_launch(void* const* d_in, const int* in_sizes, int n_in,
                              void* d_out, int out_size)
{
    const int*   user_id       = (const int*)d_in[0];
    const int*   item_id       = (const int*)d_in[1];
    const int*   item_category = (const int*)d_in[2];
    const int*   item_dur_bkt  = (const int*)d_in[3];
    const float* user_dense    = (const float*)d_in[4];
    const float* item_dense    = (const float*)d_in[5];
    const int*   history_seq   = (const int*)d_in[6];
    const float* user_W        = (const float*)d_in[7];
    const float* item_W        = (const float*)d_in[8];
    const float* cat_W         = (const float*)d_in[9];
    const float* dur_W         = (const float*)d_in[10];
    const float* hist_W        = (const float*)d_in[11];
    const float* aW0 = (const float*)d_in[12];
    const float* ab0 = (const float*)d_in[13];
    const float* aW1 = (const float*)d_in[14];
    const float* ab1 = (const float*)d_in[15];
    const float* aW2 = (const float*)d_in[16];
    const float* ab2 = (const float*)d_in[17];
    const float* mW0 = (const float*)d_in[18];
    const float* mb0 = (const float*)d_in[19];
    const float* mW1 = (const float*)d_in[20];
    const float* mb1 = (const float*)d_in[21];
    const float* mW2 = (const float*)d_in[22];
    const float* mb2 = (const float*)d_in[23];

    const int B = in_sizes[0];
    float* out = (float*)d_out;

    cudaFuncSetAttribute(attn_kernel, cudaFuncAttributeMaxDynamicSharedMemorySize,
                         (int)sizeof(SmemA));

    attn_kernel<<<B, 256, sizeof(SmemA)>>>(
        user_id, item_id, item_category, item_dur_bkt,
        user_dense, item_dense, history_seq,
        user_W, item_W, cat_W, dur_W, hist_W,
        aW0, ab0, aW1, ab1, aW2, ab2);

    mlp_kernel<<<(B + 15) / 16, 256>>>(mW0, mb0, mW1, mb1, mW2, mb2, out, B);
}

// round 8
// speedup vs baseline: 2.7345x; 1.0845x over previous
#include <cuda_runtime.h>
#include <math.h>

#define LSEQ 200
#define HSTR 68      // histL row stride (floats)
#define MP_STR 68    // Mp row stride (uint2)
#define W1P_STR 36   // aW1p row stride (uint2)
#define NTHR 416     // 13 warps: one l-tile per warp
#define B_MAX 4096

__device__ float g_xbuf[B_MAX * 244];

typedef unsigned long long u64t;
typedef unsigned int u32t;

__device__ __forceinline__ u64t dup2(float x) {
    u64t r; asm("mov.b64 %0, {%1, %1};" : "=l"(r) : "f"(x)); return r;
}
__device__ __forceinline__ void fma2(u64t& d, u64t a, u64t b) {
    asm("fma.rn.f32x2 %0, %1, %2, %0;" : "+l"(d) : "l"(a), "l"(b));
}
__device__ __forceinline__ void unpack2(u64t v, float& a, float& b) {
    asm("mov.b64 {%0, %1}, %2;" : "=f"(a), "=f"(b) : "l"(v));
}
__device__ __forceinline__ u32t f2tf32(float f) {
    u32t u; asm("cvt.rna.tf32.f32 %0, %1;" : "=r"(u) : "f"(f)); return u;
}
__device__ __forceinline__ void mma_tf32(float& d0, float& d1, float& d2, float& d3,
                                         u32t a0, u32t a1, u32t a2, u32t a3,
                                         u32t b0, u32t b1) {
    asm volatile(
        "mma.sync.aligned.m16n8k8.row.col.f32.tf32.tf32.f32 "
        "{%0,%1,%2,%3},{%4,%5,%6,%7},{%8,%9},{%0,%1,%2,%3};"
        : "+f"(d0), "+f"(d1), "+f"(d2), "+f"(d3)
        : "r"(a0), "r"(a1), "r"(a2), "r"(a3), "r"(b0), "r"(b1));
}

struct __align__(16) SmemA {
    float histL[208 * HSTR];     // [l][k] fp32, rows 200..207 zero
    uint2 Mp[32 * MP_STR];       // packed tf32 M pairs
    uint2 aW1p[32 * W1P_STR];    // packed tf32 aW1 pairs
    float t[64];
    float c1[64];
    float ab1s[32];
    float aW2s[32];
    float scores[208];
    float red[16];
    float pool6[384];
};

__global__ __launch_bounds__(NTHR, 2) void attn_kernel(
    const int* __restrict__ user_id, const int* __restrict__ item_id,
    const int* __restrict__ item_category, const int* __restrict__ item_dur_bkt,
    const float* __restrict__ user_dense, const float* __restrict__ item_dense,
    const int* __restrict__ history_seq,
    const float* __restrict__ user_W, const float* __restrict__ item_W,
    const float* __restrict__ cat_W, const float* __restrict__ dur_W,
    const float* __restrict__ hist_W,
    const float* __restrict__ aW0, const float* __restrict__ ab0,
    const float* __restrict__ aW1, const float* __restrict__ ab1,
    const float* __restrict__ aW2, const float* __restrict__ ab2)
{
    extern __shared__ char smem_raw[];
    SmemA& S = *reinterpret_cast<SmemA*>(smem_raw);
    float* Mpf = (float*)S.Mp;
    float* W1pf = (float*)S.aW1p;
    const int b = blockIdx.x;
    const int tid = threadIdx.x;
    const int lane = tid & 31;
    const int w = tid >> 5;            // 0..12

    // ---- phase A: t, aW1p, small vectors, gather ----
    if (tid < 64) S.t[tid] = item_W[item_id[b] * 64 + tid];
    for (int p = tid; p < 2048; p += NTHR) {
        int k = p >> 5, j = p & 31;
        int kt = k >> 3, r = k & 7, tg = r & 3, half = r >> 2;
        W1pf[(((kt * 4 + tg) * W1P_STR) + j) * 2 + half] = __uint_as_float(f2tf32(aW1[p]));
    }
    if (tid >= 64 && tid < 96) { S.aW2s[tid - 64] = aW2[tid - 64]; S.ab1s[tid - 64] = ab1[tid - 64]; }
    {
        int c8 = tid & 7;
        for (int l = tid >> 3; l < LSEQ; l += NTHR / 8) {
            int row = history_seq[b * LSEQ + l];
            const float4* rp = (const float4*)&hist_W[row * 64];
            float4 v0 = rp[c8 * 2], v1 = rp[c8 * 2 + 1];
            *(float4*)&S.histL[l * HSTR + c8 * 8]     = v0;
            *(float4*)&S.histL[l * HSTR + c8 * 8 + 4] = v1;
        }
    }
    for (int p = tid; p < 8 * 64; p += NTHR)
        S.histL[(LSEQ + (p >> 6)) * HSTR + (p & 63)] = 0.f;

    // ---- phase B: Mp (tf32 packed) + c1 partials ----
    for (int idx = tid; idx < 4096; idx += NTHR) {
        int k = idx >> 6, j = idx & 63;
        float v = aW0[idx] + aW0[(192 + k) * 64 + j] + S.t[k] * aW0[(128 + k) * 64 + j];
        int kt = k >> 3, r = k & 7, tg = r & 3, half = r >> 2;
        Mpf[(((kt * 4 + tg) * MP_STR) + j) * 2 + half] = __uint_as_float(f2tf32(v));
    }
    if (tid < 256) {
        int j = tid & 63, kq = tid >> 6;
        float s = 0.f;
        #pragma unroll 4
        for (int k = kq * 16; k < kq * 16 + 16; k++)
            s += S.t[k] * (aW0[(64 + k) * 64 + j] - aW0[(192 + k) * 64 + j]);
        S.pool6[tid] = s;
    }
    __syncthreads();
    if (tid < 64)
        S.c1[tid] = ab0[tid] + S.pool6[tid] + S.pool6[64 + tid]
                  + S.pool6[128 + tid] + S.pool6[192 + tid];
    __syncthreads();

    // ---- tensor-core attention: warp w owns l-tile w ----
    const int gid = lane >> 2;   // 0..7
    const int tig = lane & 3;    // 0..3
    const bool odd = tig & 1;
    const int src0 = gid * 4 + (tig >> 1);
    const int src2 = src0 + 2;
    const float ab2v = ab2[0];

    {
        const int l0 = w * 16;

        // GEMM1: C1[16 x 64] = hist[16 x 64] * M[64 x 64]
        float C1[8][4] = {};
        #pragma unroll
        for (int kt = 0; kt < 8; kt++) {
            const float* ap = &S.histL[(l0 + gid) * HSTR + kt * 8 + tig];
            u32t ua0 = f2tf32(ap[0]);
            u32t ua1 = f2tf32(ap[8 * HSTR]);
            u32t ua2 = f2tf32(ap[4]);
            u32t ua3 = f2tf32(ap[8 * HSTR + 4]);
            const uint2* bp = &S.Mp[(kt * 4 + tig) * MP_STR + gid];
            #pragma unroll
            for (int jt = 0; jt < 8; jt++) {
                uint2 bb = bp[jt * 8];
                mma_tf32(C1[jt][0], C1[jt][1], C1[jt][2], C1[jt][3],
                         ua0, ua1, ua2, ua3, bb.x, bb.y);
            }
        }
        // bias + relu (h0 stays in registers)
        #pragma unroll
        for (int jt = 0; jt < 8; jt++) {
            float cb0 = S.c1[jt * 8 + 2 * tig], cb1 = S.c1[jt * 8 + 2 * tig + 1];
            C1[jt][0] = fmaxf(C1[jt][0] + cb0, 0.f);
            C1[jt][1] = fmaxf(C1[jt][1] + cb1, 0.f);
            C1[jt][2] = fmaxf(C1[jt][2] + cb0, 0.f);
            C1[jt][3] = fmaxf(C1[jt][3] + cb1, 0.f);
        }

        // GEMM2: C2[16 x 32] = h0[16 x 64] * aW1[64 x 32]; A frags via shfl
        float C2[4][4] = {};
        #pragma unroll
        for (int kt = 0; kt < 8; kt++) {
            float v00 = __shfl_sync(0xffffffffu, C1[kt][0], src0);
            float v01 = __shfl_sync(0xffffffffu, C1[kt][1], src0);
            float v10 = __shfl_sync(0xffffffffu, C1[kt][2], src0);
            float v11 = __shfl_sync(0xffffffffu, C1[kt][3], src0);
            float v20 = __shfl_sync(0xffffffffu, C1[kt][0], src2);
            float v21 = __shfl_sync(0xffffffffu, C1[kt][1], src2);
            float v30 = __shfl_sync(0xffffffffu, C1[kt][2], src2);
            float v31 = __shfl_sync(0xffffffffu, C1[kt][3], src2);
            u32t ua0 = f2tf32(odd ? v01 : v00);
            u32t ua1 = f2tf32(odd ? v11 : v10);
            u32t ua2 = f2tf32(odd ? v21 : v20);
            u32t ua3 = f2tf32(odd ? v31 : v30);
            const uint2* bp = &S.aW1p[(kt * 4 + tig) * W1P_STR + gid];
            #pragma unroll
            for (int jt = 0; jt < 4; jt++) {
                uint2 bb = bp[jt * 8];
                mma_tf32(C2[jt][0], C2[jt][1], C2[jt][2], C2[jt][3],
                         ua0, ua1, ua2, ua3, bb.x, bb.y);
            }
        }
        // scores: relu(h1 + ab1) . aW2, reduce over the 4 tig lanes
        float sr = 0.f, sr8 = 0.f;
        #pragma unroll
        for (int jt = 0; jt < 4; jt++) {
            int j = jt * 8 + 2 * tig;
            float b0v = S.ab1s[j], b1v = S.ab1s[j + 1];
            float w0v = S.aW2s[j], w1v = S.aW2s[j + 1];
            sr  += fmaxf(C2[jt][0] + b0v, 0.f) * w0v + fmaxf(C2[jt][1] + b1v, 0.f) * w1v;
            sr8 += fmaxf(C2[jt][2] + b0v, 0.f) * w0v + fmaxf(C2[jt][3] + b1v, 0.f) * w1v;
        }
        sr  += __shfl_xor_sync(0xffffffffu, sr, 1);
        sr  += __shfl_xor_sync(0xffffffffu, sr, 2);
        sr8 += __shfl_xor_sync(0xffffffffu, sr8, 1);
        sr8 += __shfl_xor_sync(0xffffffffu, sr8, 2);
        if (tig == 0) {
            S.scores[l0 + gid]     = sr + ab2v;
            S.scores[l0 + gid + 8] = sr8 + ab2v;
        }
    }
    __syncthreads();

    // ---- mask + softmax over L (13 warps) ----
    {
        float s = -3.402823466e38f;
        if (tid < LSEQ) {
            s = S.scores[tid];
            if (history_seq[b * LSEQ + tid] == 0) s = -1.0e9f;
        }
        float v = s;
        #pragma unroll
        for (int o = 16; o; o >>= 1) v = fmaxf(v, __shfl_xor_sync(0xffffffffu, v, o));
        if (lane == 0) S.red[w] = v;
        __syncthreads();
        if (tid < 32) {
            float r = (tid < 13) ? S.red[tid] : -3.402823466e38f;
            #pragma unroll
            for (int o = 8; o; o >>= 1) r = fmaxf(r, __shfl_xor_sync(0xffffffffu, r, o));
            if (tid == 0) S.red[13] = r;
        }
        __syncthreads();
        float mx = S.red[13];
        float e = (tid < LSEQ) ? expf(s - mx) : 0.f;
        float v2 = e;
        #pragma unroll
        for (int o = 16; o; o >>= 1) v2 += __shfl_xor_sync(0xffffffffu, v2, o);
        if (lane == 0) S.red[w] = v2;
        __syncthreads();
        if (tid < 32) {
            float r = (tid < 13) ? S.red[tid] : 0.f;
            #pragma unroll
            for (int o = 8; o; o >>= 1) r += __shfl_xor_sync(0xffffffffu, r, o);
            if (tid == 0) S.red[13] = r;
        }
        __syncthreads();
        float inv = 1.f / S.red[13];
        if (tid < LSEQ) S.scores[tid] = e * inv;
    }
    __syncthreads();

    // ---- pooled[k] = sum_l w[l]*hist[l][k] (fp32 exact); 6 groups of 64 ----
    if (tid < 384) {
        int k = tid & 63, g = tid >> 6;
        float p = 0.f;
        for (int l = g; l < LSEQ; l += 6) p += S.histL[l * HSTR + k] * S.scores[l];
        S.pool6[(g << 6) + k] = p;
    }
    __syncthreads();
    if (tid < 64) {
        float pooled = S.pool6[tid] + S.pool6[64 + tid] + S.pool6[128 + tid]
                     + S.pool6[192 + tid] + S.pool6[256 + tid] + S.pool6[320 + tid];
        g_xbuf[b * 244 + 180 + tid] = pooled;
    }
    // ---- assemble x ----
    if (tid < 64) {
        g_xbuf[b * 244 + tid] = user_W[user_id[b] * 64 + tid];
    } else if (tid < 128) {
        g_xbuf[b * 244 + tid] = S.t[tid - 64];
    } else if (tid < 144) {
        g_xbuf[b * 244 + tid] = cat_W[item_category[b] * 16 + (tid - 128)];
    } else if (tid < 152) {
        g_xbuf[b * 244 + tid] = dur_W[item_dur_bkt[b] * 8 + (tid - 144)];
    } else if (tid < 177) {
        g_xbuf[b * 244 + tid] = user_dense[b * 25 + (tid - 152)];
    } else if (tid < 180) {
        g_xbuf[b * 244 + tid] = item_dense[b * 3 + (tid - 177)];
    }
}

// ---- MLP: 16 samples/block, 4-weight batches, 3 blocks/SM ----
__global__ __launch_bounds__(256, 3) void mlp_kernel(
    const float* __restrict__ mW0, const float* __restrict__ mb0,
    const float* __restrict__ mW1, const float* __restrict__ mb1,
    const float* __restrict__ mW2, const float* __restrict__ mb2,
    float* __restrict__ out, int B)
{
    __shared__ __align__(16) float xsA[244 * 8];
    __shared__ __align__(16) float xsB[244 * 8];
    __shared__ __align__(16) float h0A[256 * 8];
    __shared__ __align__(16) float h0B[256 * 8];
    __shared__ __align__(16) float h1s[16 * 128];
    const int b0 = blockIdx.x * 16;
    const int tid = threadIdx.x;

    #pragma unroll
    for (int q = 0; q < 8; q++) {
        if (tid < 244) {
            if (b0 + q < B)     xsA[tid * 8 + q] = g_xbuf[(b0 + q) * 244 + tid];
            if (b0 + 8 + q < B) xsB[tid * 8 + q] = g_xbuf[(b0 + 8 + q) * 244 + tid];
        }
    }
    __syncthreads();

    // layer 0: 244 -> 256, 16 samples (8 fma2 per weight load)
    {
        u64t acc[8];
        u64t bias = dup2(mb0[tid]);
        #pragma unroll
        for (int p = 0; p < 8; p++) acc[p] = bias;
        #pragma unroll 1
        for (int i = 0; i < 244; i += 4) {
            float wv[4];
            #pragma unroll
            for (int u = 0; u < 4; u++) wv[u] = mW0[(i + u) * 256 + tid];
            #pragma unroll
            for (int u = 0; u < 4; u++) {
                u64t wd = dup2(wv[u]);
                ulonglong2 a01 = *(const ulonglong2*)&xsA[(i + u) * 8];
                ulonglong2 a23 = *(const ulonglong2*)&xsA[(i + u) * 8 + 4];
                ulonglong2 b01 = *(const ulonglong2*)&xsB[(i + u) * 8];
                ulonglong2 b23 = *(const ulonglong2*)&xsB[(i + u) * 8 + 4];
                fma2(acc[0], a01.x, wd); fma2(acc[1], a01.y, wd);
                fma2(acc[2], a23.x, wd); fma2(acc[3], a23.y, wd);
                fma2(acc[4], b01.x, wd); fma2(acc[5], b01.y, wd);
                fma2(acc[6], b23.x, wd); fma2(acc[7], b23.y, wd);
            }
        }
        #pragma unroll
        for (int p = 0; p < 4; p++) {
            float a, c;
            unpack2(acc[p], a, c);
            h0A[tid * 8 + 2 * p]     = fmaxf(a, 0.f);
            h0A[tid * 8 + 2 * p + 1] = fmaxf(c, 0.f);
            unpack2(acc[4 + p], a, c);
            h0B[tid * 8 + 2 * p]     = fmaxf(a, 0.f);
            h0B[tid * 8 + 2 * p + 1] = fmaxf(c, 0.f);
        }
    }
    __syncthreads();

    // layer 1: 256 -> 128; half h handles group A or B (8 samples)
    {
        int j = tid & 127, h = tid >> 7;
        const float* h0p = h ? h0B : h0A;
        u64t bias = dup2(mb1[j]);
        u64t acc[4] = {bias, bias, bias, bias};
        #pragma unroll 1
        for (int i = 0; i < 256; i += 4) {
            float wv[4];
            #pragma unroll
            for (int u = 0; u < 4; u++) wv[u] = mW1[(i + u) * 128 + j];
            #pragma unroll
            for (int u = 0; u < 4; u++) {
                u64t wd = dup2(wv[u]);
                ulonglong2 a01 = *(const ulonglong2*)&h0p[(i + u) * 8];
                ulonglong2 a23 = *(const ulonglong2*)&h0p[(i + u) * 8 + 4];
                fma2(acc[0], a01.x, wd); fma2(acc[1], a01.y, wd);
                fma2(acc[2], a23.x, wd); fma2(acc[3], a23.y, wd);
            }
        }
        #pragma unroll
        for (int p = 0; p < 4; p++) {
            float a, c;
            unpack2(acc[p], a, c);
            h1s[(h * 8 + 2 * p) * 128 + j]     = fmaxf(a, 0.f);
            h1s[(h * 8 + 2 * p + 1) * 128 + j] = fmaxf(c, 0.f);
        }
    }
    __syncthreads();

    // layer 2: 128 -> 1, sigmoid; warp w handles samples w and w+8
    {
        int wsel = tid >> 5, lane = tid & 31;
        float m0 = mW2[lane], m1 = mW2[lane + 32], m2 = mW2[lane + 64], m3 = mW2[lane + 96];
        #pragma unroll
        for (int g = 0; g < 2; g++) {
            int s = wsel + g * 8;
            const float* hp = &h1s[s * 128];
            float v = hp[lane] * m0 + hp[lane + 32] * m1 + hp[lane + 64] * m2 + hp[lane + 96] * m3;
            #pragma unroll
            for (int o = 16; o; o >>= 1) v += __shfl_xor_sync(0xffffffffu, v, o);
            if (lane == 0 && (b0 + s) < B) {
                float logit = v + mb2[0];
                out[b0 + s] = 1.f / (1.f + expf(-logit));
            }
        }
    }
}

extern "C" void kernel_launch(void* const* d_in, const int* in_sizes, int n_in,
                              void* d_out, int out_size)
{
    const int*   user_id       = (const int*)d_in[0];
    const int*   item_id       = (const int*)d_in[1];
    const int*   item_category = (const int*)d_in[2];
    const int*   item_dur_bkt  = (const int*)d_in[3];
    const float* user_dense    = (const float*)d_in[4];
    const float* item_dense    = (const float*)d_in[5];
    const int*   history_seq   = (const int*)d_in[6];
    const float* user_W        = (const float*)d_in[7];
    const float* item_W        = (const float*)d_in[8];
    const float* cat_W         = (const float*)d_in[9];
    const float* dur_W         = (const float*)d_in[10];
    const float* hist_W        = (const float*)d_in[11];
    const float* aW0 = (const float*)d_in[12];
    const float* ab0 = (const float*)d_in[13];
    const float* aW1 = (const float*)d_in[14];
    const float* ab1 = (const float*)d_in[15];
    const float* aW2 = (const float*)d_in[16];
    const float* ab2 = (const float*)d_in[17];
    const float* mW0 = (const float*)d_in[18];
    const float* mb0 = (const float*)d_in[19];
    const float* mW1 = (const float*)d_in[20];
    const float* mb1 = (const float*)d_in[21];
    const float* mW2 = (const float*)d_in[22];
    const float* mb2 = (const float*)d_in[23];

    const int B = in_sizes[0];
    float* out = (float*)d_out;

    cudaFuncSetAttribute(attn_kernel, cudaFuncAttributeMaxDynamicSharedMemorySize,
                         (int)sizeof(SmemA));

    attn_kernel<<<B, NTHR, sizeof(SmemA)>>>(
        user_id, item_id, item_category, item_dur_bkt,
        user_dense, item_dense, history_seq,
        user_W, item_W, cat_W, dur_W, hist_W,
        aW0, ab0, aW1, ab1, aW2, ab2);

    mlp_kernel<<<(B + 15) / 16, 256>>>(mW0, mb0, mW1, mb1, mW2, mb2, out, B);
}

// round 9
// speedup vs baseline: 3.0340x; 1.1095x over previous
#include <cuda_runtime.h>
#include <math.h>

#define LSEQ 200
#define HSTR 68      // histL row stride (floats)
#define MP_STR 68    // Mp row stride (uint2)
#define W1P_STR 36   // aW1p row stride (uint2)
#define NTHR 416     // 13 warps: one l-tile per warp
#define B_MAX 4096

__device__ float g_xbuf[B_MAX * 244];

typedef unsigned long long u64t;
typedef unsigned int u32t;

__device__ __forceinline__ u64t dup2(float x) {
    u64t r; asm("mov.b64 %0, {%1, %1};" : "=l"(r) : "f"(x)); return r;
}
__device__ __forceinline__ void fma2(u64t& d, u64t a, u64t b) {
    asm("fma.rn.f32x2 %0, %1, %2, %0;" : "+l"(d) : "l"(a), "l"(b));
}
__device__ __forceinline__ void unpack2(u64t v, float& a, float& b) {
    asm("mov.b64 {%0, %1}, %2;" : "=f"(a), "=f"(b) : "l"(v));
}
__device__ __forceinline__ u32t f2tf32(float f) {
    u32t u; asm("cvt.rna.tf32.f32 %0, %1;" : "=r"(u) : "f"(f)); return u;
}
__device__ __forceinline__ void mma_tf32(float& d0, float& d1, float& d2, float& d3,
                                         u32t a0, u32t a1, u32t a2, u32t a3,
                                         u32t b0, u32t b1) {
    asm volatile(
        "mma.sync.aligned.m16n8k8.row.col.f32.tf32.tf32.f32 "
        "{%0,%1,%2,%3},{%4,%5,%6,%7},{%8,%9},{%0,%1,%2,%3};"
        : "+f"(d0), "+f"(d1), "+f"(d2), "+f"(d3)
        : "r"(a0), "r"(a1), "r"(a2), "r"(a3), "r"(b0), "r"(b1));
}

struct __align__(16) SmemA {
    float histL[208 * HSTR];     // [l][k] fp32, rows 200..207 zero
    uint2 Mp[32 * MP_STR];       // packed tf32 M pairs
    uint2 aW1p[32 * W1P_STR];    // packed tf32 aW1 pairs
    float t[64];
    float c1[64];
    float ab1s[32];
    float aW2s[32];
    float scores[208];
    float red[16];
    float pool6[384];
};

__global__ __launch_bounds__(NTHR, 2) void attn_kernel(
    const int* __restrict__ user_id, const int* __restrict__ item_id,
    const int* __restrict__ item_category, const int* __restrict__ item_dur_bkt,
    const float* __restrict__ user_dense, const float* __restrict__ item_dense,
    const int* __restrict__ history_seq,
    const float* __restrict__ user_W, const float* __restrict__ item_W,
    const float* __restrict__ cat_W, const float* __restrict__ dur_W,
    const float* __restrict__ hist_W,
    const float* __restrict__ aW0, const float* __restrict__ ab0,
    const float* __restrict__ aW1, const float* __restrict__ ab1,
    const float* __restrict__ aW2, const float* __restrict__ ab2)
{
    extern __shared__ char smem_raw[];
    SmemA& S = *reinterpret_cast<SmemA*>(smem_raw);
    float* Mpf = (float*)S.Mp;
    float* W1pf = (float*)S.aW1p;
    const int b = blockIdx.x;
    const int tid = threadIdx.x;
    const int lane = tid & 31;
    const int w = tid >> 5;            // 0..12

    // ---- phase A: t, aW1p, small vectors, gather ----
    if (tid < 64) S.t[tid] = item_W[item_id[b] * 64 + tid];
    for (int p = tid; p < 2048; p += NTHR) {
        int k = p >> 5, j = p & 31;
        int kt = k >> 3, r = k & 7, tg = r & 3, half = r >> 2;
        W1pf[(((kt * 4 + tg) * W1P_STR) + j) * 2 + half] = __uint_as_float(f2tf32(aW1[p]));
    }
    if (tid >= 64 && tid < 96) { S.aW2s[tid - 64] = aW2[tid - 64]; S.ab1s[tid - 64] = ab1[tid - 64]; }
    {
        int c8 = tid & 7;
        for (int l = tid >> 3; l < LSEQ; l += NTHR / 8) {
            int row = history_seq[b * LSEQ + l];
            const float4* rp = (const float4*)&hist_W[row * 64];
            float4 v0 = rp[c8 * 2], v1 = rp[c8 * 2 + 1];
            *(float4*)&S.histL[l * HSTR + c8 * 8]     = v0;
            *(float4*)&S.histL[l * HSTR + c8 * 8 + 4] = v1;
        }
    }
    for (int p = tid; p < 8 * 64; p += NTHR)
        S.histL[(LSEQ + (p >> 6)) * HSTR + (p & 63)] = 0.f;
    __syncthreads();   // S.t must be visible before M build reads it

    // ---- phase B: Mp (tf32 packed, float4 loads) + c1 partials ----
    for (int g4 = tid; g4 < 1024; g4 += NTHR) {
        int k = g4 >> 4, j4 = (g4 & 15) << 2;
        float tk = S.t[k];
        float4 a0v = *(const float4*)&aW0[k * 64 + j4];
        float4 a192 = *(const float4*)&aW0[(192 + k) * 64 + j4];
        float4 a128 = *(const float4*)&aW0[(128 + k) * 64 + j4];
        int kt = k >> 3, r = k & 7, tg = r & 3, half = r >> 2;
        float* dst = &Mpf[((kt * 4 + tg) * MP_STR) * 2 + half];
        dst[(j4 + 0) * 2] = __uint_as_float(f2tf32(a0v.x + a192.x + tk * a128.x));
        dst[(j4 + 1) * 2] = __uint_as_float(f2tf32(a0v.y + a192.y + tk * a128.y));
        dst[(j4 + 2) * 2] = __uint_as_float(f2tf32(a0v.z + a192.z + tk * a128.z));
        dst[(j4 + 3) * 2] = __uint_as_float(f2tf32(a0v.w + a192.w + tk * a128.w));
    }
    if (tid < 256) {
        int j = tid & 63, kq = tid >> 6;
        float s = 0.f;
        #pragma unroll 4
        for (int k = kq * 16; k < kq * 16 + 16; k++)
            s += S.t[k] * (aW0[(64 + k) * 64 + j] - aW0[(192 + k) * 64 + j]);
        S.pool6[tid] = s;
    }
    __syncthreads();
    if (tid < 64)
        S.c1[tid] = ab0[tid] + S.pool6[tid] + S.pool6[64 + tid]
                  + S.pool6[128 + tid] + S.pool6[192 + tid];
    __syncthreads();

    // ---- tensor-core attention: warp w owns l-tile w ----
    const int gid = lane >> 2;   // 0..7
    const int tig = lane & 3;    // 0..3
    const bool odd = tig & 1;
    const int src0 = gid * 4 + (tig >> 1);
    const int src2 = src0 + 2;
    const float ab2v = ab2[0];

    {
        const int l0 = w * 16;

        // GEMM1: C1[16 x 64] = hist[16 x 64] * M[64 x 64]
        float C1[8][4] = {};
        #pragma unroll
        for (int kt = 0; kt < 8; kt++) {
            const float* ap = &S.histL[(l0 + gid) * HSTR + kt * 8 + tig];
            u32t ua0 = f2tf32(ap[0]);
            u32t ua1 = f2tf32(ap[8 * HSTR]);
            u32t ua2 = f2tf32(ap[4]);
            u32t ua3 = f2tf32(ap[8 * HSTR + 4]);
            const uint2* bp = &S.Mp[(kt * 4 + tig) * MP_STR + gid];
            #pragma unroll
            for (int jt = 0; jt < 8; jt++) {
                uint2 bb = bp[jt * 8];
                mma_tf32(C1[jt][0], C1[jt][1], C1[jt][2], C1[jt][3],
                         ua0, ua1, ua2, ua3, bb.x, bb.y);
            }
        }
        // bias + relu (h0 stays in registers)
        #pragma unroll
        for (int jt = 0; jt < 8; jt++) {
            float cb0 = S.c1[jt * 8 + 2 * tig], cb1 = S.c1[jt * 8 + 2 * tig + 1];
            C1[jt][0] = fmaxf(C1[jt][0] + cb0, 0.f);
            C1[jt][1] = fmaxf(C1[jt][1] + cb1, 0.f);
            C1[jt][2] = fmaxf(C1[jt][2] + cb0, 0.f);
            C1[jt][3] = fmaxf(C1[jt][3] + cb1, 0.f);
        }

        // GEMM2: C2[16 x 32] = h0[16 x 64] * aW1[64 x 32]; A frags via shfl
        float C2[4][4] = {};
        #pragma unroll
        for (int kt = 0; kt < 8; kt++) {
            float v00 = __shfl_sync(0xffffffffu, C1[kt][0], src0);
            float v01 = __shfl_sync(0xffffffffu, C1[kt][1], src0);
            float v10 = __shfl_sync(0xffffffffu, C1[kt][2], src0);
            float v11 = __shfl_sync(0xffffffffu, C1[kt][3], src0);
            float v20 = __shfl_sync(0xffffffffu, C1[kt][0], src2);
            float v21 = __shfl_sync(0xffffffffu, C1[kt][1], src2);
            float v30 = __shfl_sync(0xffffffffu, C1[kt][2], src2);
            float v31 = __shfl_sync(0xffffffffu, C1[kt][3], src2);
            u32t ua0 = f2tf32(odd ? v01 : v00);
            u32t ua1 = f2tf32(odd ? v11 : v10);
            u32t ua2 = f2tf32(odd ? v21 : v20);
            u32t ua3 = f2tf32(odd ? v31 : v30);
            const uint2* bp = &S.aW1p[(kt * 4 + tig) * W1P_STR + gid];
            #pragma unroll
            for (int jt = 0; jt < 4; jt++) {
                uint2 bb = bp[jt * 8];
                mma_tf32(C2[jt][0], C2[jt][1], C2[jt][2], C2[jt][3],
                         ua0, ua1, ua2, ua3, bb.x, bb.y);
            }
        }
        // scores: relu(h1 + ab1) . aW2, reduce over the 4 tig lanes
        float sr = 0.f, sr8 = 0.f;
        #pragma unroll
        for (int jt = 0; jt < 4; jt++) {
            int j = jt * 8 + 2 * tig;
            float b0v = S.ab1s[j], b1v = S.ab1s[j + 1];
            float w0v = S.aW2s[j], w1v = S.aW2s[j + 1];
            sr  += fmaxf(C2[jt][0] + b0v, 0.f) * w0v + fmaxf(C2[jt][1] + b1v, 0.f) * w1v;
            sr8 += fmaxf(C2[jt][2] + b0v, 0.f) * w0v + fmaxf(C2[jt][3] + b1v, 0.f) * w1v;
        }
        sr  += __shfl_xor_sync(0xffffffffu, sr, 1);
        sr  += __shfl_xor_sync(0xffffffffu, sr, 2);
        sr8 += __shfl_xor_sync(0xffffffffu, sr8, 1);
        sr8 += __shfl_xor_sync(0xffffffffu, sr8, 2);
        if (tig == 0) {
            S.scores[l0 + gid]     = sr + ab2v;
            S.scores[l0 + gid + 8] = sr8 + ab2v;
        }
    }
    __syncthreads();

    // ---- mask + softmax over L (13 warps) ----
    {
        float s = -3.402823466e38f;
        if (tid < LSEQ) {
            s = S.scores[tid];
            if (history_seq[b * LSEQ + tid] == 0) s = -1.0e9f;
        }
        float v = s;
        #pragma unroll
        for (int o = 16; o; o >>= 1) v = fmaxf(v, __shfl_xor_sync(0xffffffffu, v, o));
        if (lane == 0) S.red[w] = v;
        __syncthreads();
        if (tid < 32) {
            float r = (tid < 13) ? S.red[tid] : -3.402823466e38f;
            #pragma unroll
            for (int o = 8; o; o >>= 1) r = fmaxf(r, __shfl_xor_sync(0xffffffffu, r, o));
            if (tid == 0) S.red[13] = r;
        }
        __syncthreads();
        float mx = S.red[13];
        float e = (tid < LSEQ) ? expf(s - mx) : 0.f;
        float v2 = e;
        #pragma unroll
        for (int o = 16; o; o >>= 1) v2 += __shfl_xor_sync(0xffffffffu, v2, o);
        if (lane == 0) S.red[w] = v2;
        __syncthreads();
        if (tid < 32) {
            float r = (tid < 13) ? S.red[tid] : 0.f;
            #pragma unroll
            for (int o = 8; o; o >>= 1) r += __shfl_xor_sync(0xffffffffu, r, o);
            if (tid == 0) S.red[13] = r;
        }
        __syncthreads();
        float inv = 1.f / S.red[13];
        if (tid < LSEQ) S.scores[tid] = e * inv;
    }
    __syncthreads();

    // ---- pooled[k] = sum_l w[l]*hist[l][k] (fp32 exact); 6 groups of 64 ----
    if (tid < 384) {
        int k = tid & 63, g = tid >> 6;
        float p = 0.f;
        for (int l = g; l < LSEQ; l += 6) p += S.histL[l * HSTR + k] * S.scores[l];
        S.pool6[(g << 6) + k] = p;
    }
    __syncthreads();
    if (tid < 64) {
        float pooled = S.pool6[tid] + S.pool6[64 + tid] + S.pool6[128 + tid]
                     + S.pool6[192 + tid] + S.pool6[256 + tid] + S.pool6[320 + tid];
        g_xbuf[b * 244 + 180 + tid] = pooled;
    }
    // ---- assemble x ----
    if (tid < 64) {
        g_xbuf[b * 244 + tid] = user_W[user_id[b] * 64 + tid];
    } else if (tid < 128) {
        g_xbuf[b * 244 + tid] = S.t[tid - 64];
    } else if (tid < 144) {
        g_xbuf[b * 244 + tid] = cat_W[item_category[b] * 16 + (tid - 128)];
    } else if (tid < 152) {
        g_xbuf[b * 244 + tid] = dur_W[item_dur_bkt[b] * 8 + (tid - 144)];
    } else if (tid < 177) {
        g_xbuf[b * 244 + tid] = user_dense[b * 25 + (tid - 152)];
    } else if (tid < 180) {
        g_xbuf[b * 244 + tid] = item_dense[b * 3 + (tid - 177)];
    }
}

// ---- MLP: 16 samples/block as two 8-sample groups, f32x2, 8-weight batches (R7 config) ----
__global__ __launch_bounds__(256, 2) void mlp_kernel(
    const float* __restrict__ mW0, const float* __restrict__ mb0,
    const float* __restrict__ mW1, const float* __restrict__ mb1,
    const float* __restrict__ mW2, const float* __restrict__ mb2,
    float* __restrict__ out, int B)
{
    __shared__ __align__(16) float xsA[244 * 8];
    __shared__ __align__(16) float xsB[244 * 8];
    __shared__ __align__(16) float h0A[256 * 8];
    __shared__ __align__(16) float h0B[256 * 8];
    __shared__ __align__(16) float h1s[16 * 128];
    const int b0 = blockIdx.x * 16;
    const int tid = threadIdx.x;

    #pragma unroll
    for (int q = 0; q < 8; q++) {
        if (tid < 244) {
            if (b0 + q < B)     xsA[tid * 8 + q] = g_xbuf[(b0 + q) * 244 + tid];
            if (b0 + 8 + q < B) xsB[tid * 8 + q] = g_xbuf[(b0 + 8 + q) * 244 + tid];
        }
    }
    __syncthreads();

    // layer 0: 244 -> 256, 16 samples (8 fma2 per weight load)
    {
        u64t acc[8];
        u64t bias = dup2(mb0[tid]);
        #pragma unroll
        for (int p = 0; p < 8; p++) acc[p] = bias;
        #pragma unroll 1
        for (int i = 0; i < 240; i += 8) {
            float wv[8];
            #pragma unroll
            for (int u = 0; u < 8; u++) wv[u] = mW0[(i + u) * 256 + tid];
            #pragma unroll
            for (int u = 0; u < 8; u++) {
                u64t wd = dup2(wv[u]);
                ulonglong2 a01 = *(const ulonglong2*)&xsA[(i + u) * 8];
                ulonglong2 a23 = *(const ulonglong2*)&xsA[(i + u) * 8 + 4];
                ulonglong2 b01 = *(const ulonglong2*)&xsB[(i + u) * 8];
                ulonglong2 b23 = *(const ulonglong2*)&xsB[(i + u) * 8 + 4];
                fma2(acc[0], a01.x, wd); fma2(acc[1], a01.y, wd);
                fma2(acc[2], a23.x, wd); fma2(acc[3], a23.y, wd);
                fma2(acc[4], b01.x, wd); fma2(acc[5], b01.y, wd);
                fma2(acc[6], b23.x, wd); fma2(acc[7], b23.y, wd);
            }
        }
        #pragma unroll
        for (int i = 240; i < 244; i++) {
            u64t wd = dup2(mW0[i * 256 + tid]);
            ulonglong2 a01 = *(const ulonglong2*)&xsA[i * 8];
            ulonglong2 a23 = *(const ulonglong2*)&xsA[i * 8 + 4];
            ulonglong2 b01 = *(const ulonglong2*)&xsB[i * 8];
            ulonglong2 b23 = *(const ulonglong2*)&xsB[i * 8 + 4];
            fma2(acc[0], a01.x, wd); fma2(acc[1], a01.y, wd);
            fma2(acc[2], a23.x, wd); fma2(acc[3], a23.y, wd);
            fma2(acc[4], b01.x, wd); fma2(acc[5], b01.y, wd);
            fma2(acc[6], b23.x, wd); fma2(acc[7], b23.y, wd);
        }
        #pragma unroll
        for (int p = 0; p < 4; p++) {
            float a, c;
            unpack2(acc[p], a, c);
            h0A[tid * 8 + 2 * p]     = fmaxf(a, 0.f);
            h0A[tid * 8 + 2 * p + 1] = fmaxf(c, 0.f);
            unpack2(acc[4 + p], a, c);
            h0B[tid * 8 + 2 * p]     = fmaxf(a, 0.f);
            h0B[tid * 8 + 2 * p + 1] = fmaxf(c, 0.f);
        }
    }
    __syncthreads();

    // layer 1: 256 -> 128; half h handles group A or B (8 samples)
    {
        int j = tid & 127, h = tid >> 7;
        const float* h0p = h ? h0B : h0A;
        u64t bias = dup2(mb1[j]);
        u64t acc[4] = {bias, bias, bias, bias};
        #pragma unroll 1
        for (int i = 0; i < 256; i += 8) {
            float wv[8];
            #pragma unroll
            for (int u = 0; u < 8; u++) wv[u] = mW1[(i + u) * 128 + j];
            #pragma unroll
            for (int u = 0; u < 8; u++) {
                u64t wd = dup2(wv[u]);
                ulonglong2 a01 = *(const ulonglong2*)&h0p[(i + u) * 8];
                ulonglong2 a23 = *(const ulonglong2*)&h0p[(i + u) * 8 + 4];
                fma2(acc[0], a01.x, wd); fma2(acc[1], a01.y, wd);
                fma2(acc[2], a23.x, wd); fma2(acc[3], a23.y, wd);
            }
        }
        #pragma unroll
        for (int p = 0; p < 4; p++) {
            float a, c;
            unpack2(acc[p], a, c);
            h1s[(h * 8 + 2 * p) * 128 + j]     = fmaxf(a, 0.f);
            h1s[(h * 8 + 2 * p + 1) * 128 + j] = fmaxf(c, 0.f);
        }
    }
    __syncthreads();

    // layer 2: 128 -> 1, sigmoid; warp w handles samples w and w+8
    {
        int wsel = tid >> 5, lane = tid & 31;
        float m0 = mW2[lane], m1 = mW2[lane + 32], m2 = mW2[lane + 64], m3 = mW2[lane + 96];
        #pragma unroll
        for (int g = 0; g < 2; g++) {
            int s = wsel + g * 8;
            const float* hp = &h1s[s * 128];
            float v = hp[lane] * m0 + hp[lane + 32] * m1 + hp[lane + 64] * m2 + hp[lane + 96] * m3;
            #pragma unroll
            for (int o = 16; o; o >>= 1) v += __shfl_xor_sync(0xffffffffu, v, o);
            if (lane == 0 && (b0 + s) < B) {
                float logit = v + mb2[0];
                out[b0 + s] = 1.f / (1.f + expf(-logit));
            }
        }
    }
}

extern "C" void kernel_launch(void* const* d_in, const int* in_sizes, int n_in,
                              void* d_out, int out_size)
{
    const int*   user_id       = (const int*)d_in[0];
    const int*   item_id       = (const int*)d_in[1];
    const int*   item_category = (const int*)d_in[2];
    const int*   item_dur_bkt  = (const int*)d_in[3];
    const float* user_dense    = (const float*)d_in[4];
    const float* item_dense    = (const float*)d_in[5];
    const int*   history_seq   = (const int*)d_in[6];
    const float* user_W        = (const float*)d_in[7];
    const float* item_W        = (const float*)d_in[8];
    const float* cat_W         = (const float*)d_in[9];
    const float* dur_W         = (const float*)d_in[10];
    const float* hist_W        = (const float*)d_in[11];
    const float* aW0 = (const float*)d_in[12];
    const float* ab0 = (const float*)d_in[13];
    const float* aW1 = (const float*)d_in[14];
    const float* ab1 = (const float*)d_in[15];
    const float* aW2 = (const float*)d_in[16];
    const float* ab2 = (const float*)d_in[17];
    const float* mW0 = (const float*)d_in[18];
    const float* mb0 = (const float*)d_in[19];
    const float* mW1 = (const float*)d_in[20];
    const float* mb1 = (const float*)d_in[21];
    const float* mW2 = (const float*)d_in[22];
    const float* mb2 = (const float*)d_in[23];

    const int B = in_sizes[0];
    float* out = (float*)d_out;

    cudaFuncSetAttribute(attn_kernel, cudaFuncAttributeMaxDynamicSharedMemorySize,
                         (int)sizeof(SmemA));

    attn_kernel<<<B, NTHR, sizeof(SmemA)>>>(
        user_id, item_id, item_category, item_dur_bkt,
        user_dense, item_dense, history_seq,
        user_W, item_W, cat_W, dur_W, hist_W,
        aW0, ab0, aW1, ab1, aW2, ab2);

    mlp_kernel<<<(B + 15) / 16, 256>>>(mW0, mb0, mW1, mb1, mW2, mb2, out, B);
}